// round 2
// baseline (speedup 1.0000x reference)
#include <cuda_runtime.h>
#include <math.h>

#define Tt 512
#define SEQSZ (128*512*128)
#define OFF_EMU 16384
#define OFF_ESG (OFF_EMU + 1*SEQSZ)
#define OFF_DMU (OFF_EMU + 2*SEQSZ)
#define OFF_DSG (OFF_EMU + 3*SEQSZ)
#define OFF_PMU (OFF_EMU + 4*SEQSZ)
#define OFF_PSG (OFF_EMU + 5*SEQSZ)

// scratch (static device globals; no runtime alloc)
__device__ float g_Gx[65536*1024];  // row b*T+t: x-contrib to gates (+biases folded)
__device__ float g_Ex[65536*128];   // row b*T+t: x-contrib to enc_h preact (+biases folded)
__device__ float g_h [65536*256];   // row t*128+b: h INPUT at step t
__device__ float g_z1[65536*128];   // row t*128+b
__device__ float g_PH[65536*128];
__device__ float g_DH[65536*128];
__device__ float g_Wgx[128*1024];
__device__ float g_Wex[128*128];
__device__ float g_gb[1024];
__device__ float g_eb[128];

__device__ __forceinline__ float softplus_(float x){ return fmaxf(x,0.f)+log1pf(expf(-fabsf(x))); }
__device__ __forceinline__ float sigmoid_(float x){ return 1.f/(1.f+expf(-x)); }

// tiled SGEMM: out = act(A1@W1 [+ A2@W2] + bias). BM=128,BN=64,BK=8, 256 thr, 8x4/thr.
// btmode: rows r=t*128+b scatter to out[(b*T+t)*N+n].
__global__ __launch_bounds__(256) void gemm_k(
    const float* __restrict__ A1,int lda1,int K1,
    const float* __restrict__ A2,int lda2,int K2,
    const float* __restrict__ W1,int ldw1,
    const float* __restrict__ W2,int ldw2,
    const float* __restrict__ bias,
    float* __restrict__ out,int N,int act,int btmode)
{
    __shared__ __align__(16) float As[8][128];
    __shared__ __align__(16) float Ws[8][64];
    const int bm=blockIdx.y*128, bn=blockIdx.x*64;
    const int tid=threadIdx.x;
    const int ty=tid>>4, tx=tid&15;
    const int lr=tid>>1, lc=(tid&1)*4;
    const int wr=tid>>6, wc=tid&63;
    float acc[8][4];
    #pragma unroll
    for(int i=0;i<8;i++)
      #pragma unroll
      for(int j=0;j<4;j++) acc[i][j]=0.f;
    for(int seg=0;seg<2;seg++){
        const float* A = seg? A2:A1;
        if(A==nullptr) continue;
        const float* W = seg? W2:W1;
        const int lda=seg?lda2:lda1, ldw=seg?ldw2:ldw1, K=seg?K2:K1;
        for(int k0=0;k0<K;k0+=8){
            float4 av = *(const float4*)(A + (size_t)(bm+lr)*lda + k0+lc);
            float w0 = W[(size_t)(k0+wr)*ldw + bn+wc];
            float w1 = W[(size_t)(k0+wr+4)*ldw + bn+wc];
            __syncthreads();
            As[lc+0][lr]=av.x; As[lc+1][lr]=av.y; As[lc+2][lr]=av.z; As[lc+3][lr]=av.w;
            Ws[wr][wc]=w0; Ws[wr+4][wc]=w1;
            __syncthreads();
            #pragma unroll
            for(int kk=0;kk<8;kk++){
                float a[8],w[4];
                *(float4*)&a[0]=*(const float4*)&As[kk][ty*8];
                *(float4*)&a[4]=*(const float4*)&As[kk][ty*8+4];
                *(float4*)&w[0]=*(const float4*)&Ws[kk][tx*4];
                #pragma unroll
                for(int i=0;i<8;i++)
                  #pragma unroll
                  for(int j=0;j<4;j++) acc[i][j]=fmaf(a[i],w[j],acc[i][j]);
            }
        }
    }
    #pragma unroll
    for(int i=0;i<8;i++){
        int r=bm+ty*8+i;
        #pragma unroll
        for(int j=0;j<4;j++){
            int n=bn+tx*4+j;
            float v=acc[i][j];
            if(bias) v+=bias[n];
            if(act==1) v=fmaxf(v,0.f);
            else if(act==2) v=softplus_(v);
            size_t idx;
            if(btmode){ int b=r&127, t=r>>7; idx=((size_t)b*Tt+t)*(size_t)N+n; }
            else idx=(size_t)r*N+n;
            out[idx]=v;
        }
    }
}

// g_gb = lstm_bias + phi_x_b@Kx_top ; g_eb = enc_h_b + phi_x_b@Wenc_x_top
__global__ void bias_fold_k(const float* __restrict__ lstm_bias,
                            const float* __restrict__ lstm_kernel,
                            const float* __restrict__ enc_h_w,
                            const float* __restrict__ enc_h_b,
                            const float* __restrict__ phi_x_b)
{
    int idx=blockIdx.x*blockDim.x+threadIdx.x;
    if(idx<1024){
        float s=lstm_bias[idx];
        for(int f=0;f<128;f++) s=fmaf(phi_x_b[f],lstm_kernel[f*1024+idx],s);
        g_gb[idx]=s;
    } else if(idx<1152){
        int j=idx-1024;
        float s=enc_h_b[j];
        for(int f=0;f<128;f++) s=fmaf(phi_x_b[f],enc_h_w[f*128+j],s);
        g_eb[j]=s;
    }
}

// sequential recurrence: 64 CTAs x 2 batch rows, 256 threads, no grid sync
__global__ __launch_bounds__(256) void seq_k(
    const float* __restrict__ eps,
    const float* __restrict__ enc_h_w,
    const float* __restrict__ enc_mu_w, const float* __restrict__ enc_mu_b,
    const float* __restrict__ enc_sigma_w, const float* __restrict__ enc_sigma_b,
    const float* __restrict__ phi_z_w, const float* __restrict__ phi_z_b,
    const float* __restrict__ lstm_kernel, const float* __restrict__ lstm_rec,
    float* __restrict__ out)
{
    __shared__ __align__(16) float sh_h[2][256];
    __shared__ __align__(16) float sh_e[2][128];
    __shared__ __align__(16) float sh_z[2][128];
    __shared__ __align__(16) float sh_z1[2][128];
    __shared__ __align__(16) float sh_g[2][1024];
    const int tid=threadIdx.x;
    const int b0=blockIdx.x*2;
    const int col=tid&127, r=tid>>7;
    const int c8=(tid&127)*8;  // (d) gate cols
    const int hc=(tid&127)*2;  // h store / cell cols
    const float* Wenc_h = enc_h_w + 128*128;
    for(int i=tid;i<512;i+=256) (&sh_h[0][0])[i]=0.f;
    float creg[2]={0.f,0.f};
    __syncthreads();

    for(int t=0;t<Tt;t++){
        // store h_in for prior/dec epilogue (row t*128+b)
        {
            float2 hv=*(const float2*)&sh_h[r][hc];
            *(float2*)&g_h[(t*128 + b0 + r)*256 + hc]=hv;
        }
        // (a) enc_h = relu(Ex[b,t] + h @ Wenc_h)
        {
            float a=0.f;
            #pragma unroll 4
            for(int k=0;k<256;k++) a=fmaf(sh_h[r][k], Wenc_h[k*128+col], a);
            int e=((b0+r)*Tt+t)*128+col;
            sh_e[r][col]=fmaxf(a+g_Ex[e],0.f);
        }
        __syncthreads();
        // (b) enc_mu / enc_sigma / z + output writes
        {
            float m=0.f,s=0.f;
            #pragma unroll 4
            for(int k=0;k<128;k++){
                float e=sh_e[r][k];
                m=fmaf(e,enc_mu_w[k*128+col],m);
                s=fmaf(e,enc_sigma_w[k*128+col],s);
            }
            m+=enc_mu_b[col];
            s=softplus_(s+enc_sigma_b[col]);
            int o=((b0+r)*Tt+t)*128+col;
            out[OFF_EMU+o]=m; out[OFF_ESG+o]=s;
            sh_z[r][col]=fmaf(s,eps[o],m);
        }
        __syncthreads();
        // (c) z1 = relu(z @ phi_z_w + b)
        {
            float a=0.f;
            #pragma unroll 4
            for(int k=0;k<128;k++) a=fmaf(sh_z[r][k], phi_z_w[k*128+col], a);
            a=fmaxf(a+phi_z_b[col],0.f);
            sh_z1[r][col]=a;
            g_z1[(t*128 + b0 + r)*128 + col]=a;
            if(t==Tt-1) out[(b0+r)*128+col]=a;
        }
        __syncthreads();
        // (d) gates = Gx[b,t] + z1@Kz + h@R  (8 contiguous gate cols / thread)
        {
            float acc[8];
            int gx=((b0+r)*Tt+t)*1024 + c8;
            float4 v0=*(const float4*)&g_Gx[gx], v1=*(const float4*)&g_Gx[gx+4];
            acc[0]=v0.x;acc[1]=v0.y;acc[2]=v0.z;acc[3]=v0.w;
            acc[4]=v1.x;acc[5]=v1.y;acc[6]=v1.z;acc[7]=v1.w;
            #pragma unroll 2
            for(int k=0;k<128;k++){
                float a=sh_z1[r][k];
                const float4* wp=(const float4*)(lstm_kernel+(128+k)*1024+c8);
                float4 w0=wp[0], w1=wp[1];
                acc[0]=fmaf(a,w0.x,acc[0]); acc[1]=fmaf(a,w0.y,acc[1]);
                acc[2]=fmaf(a,w0.z,acc[2]); acc[3]=fmaf(a,w0.w,acc[3]);
                acc[4]=fmaf(a,w1.x,acc[4]); acc[5]=fmaf(a,w1.y,acc[5]);
                acc[6]=fmaf(a,w1.z,acc[6]); acc[7]=fmaf(a,w1.w,acc[7]);
            }
            #pragma unroll 2
            for(int k=0;k<256;k++){
                float a=sh_h[r][k];
                const float4* wp=(const float4*)(lstm_rec+k*1024+c8);
                float4 w0=wp[0], w1=wp[1];
                acc[0]=fmaf(a,w0.x,acc[0]); acc[1]=fmaf(a,w0.y,acc[1]);
                acc[2]=fmaf(a,w0.z,acc[2]); acc[3]=fmaf(a,w0.w,acc[3]);
                acc[4]=fmaf(a,w1.x,acc[4]); acc[5]=fmaf(a,w1.y,acc[5]);
                acc[6]=fmaf(a,w1.z,acc[6]); acc[7]=fmaf(a,w1.w,acc[7]);
            }
            *(float4*)&sh_g[r][c8]  =make_float4(acc[0],acc[1],acc[2],acc[3]);
            *(float4*)&sh_g[r][c8+4]=make_float4(acc[4],acc[5],acc[6],acc[7]);
        }
        __syncthreads();
        // LSTM cell (Keras gate order i,f,g,o), c in registers
        {
            #pragma unroll
            for(int j=0;j<2;j++){
                int cc=hc+j;
                float iv=sigmoid_(sh_g[r][cc]);
                float fv=sigmoid_(sh_g[r][256+cc]);
                float gv=tanhf(sh_g[r][512+cc]);
                float ov=sigmoid_(sh_g[r][768+cc]);
                creg[j]=fv*creg[j]+iv*gv;
                sh_h[r][cc]=ov*tanhf(creg[j]);
            }
        }
        __syncthreads();
    }
}

extern "C" void kernel_launch(void* const* d_in, const int* in_sizes, int n_in,
                              void* d_out, int out_size)
{
    (void)in_sizes;(void)n_in;(void)out_size;
    const float* x           =(const float*)d_in[0];
    const float* eps         =(const float*)d_in[1];
    const float* prior_h_w   =(const float*)d_in[2];
    const float* prior_h_b   =(const float*)d_in[3];
    const float* prior_mu_w  =(const float*)d_in[4];
    const float* prior_mu_b  =(const float*)d_in[5];
    const float* prior_sg_w  =(const float*)d_in[6];
    const float* prior_sg_b  =(const float*)d_in[7];
    const float* phi_x_w     =(const float*)d_in[8];
    const float* phi_x_b     =(const float*)d_in[9];
    const float* enc_h_w     =(const float*)d_in[10];
    const float* enc_h_b     =(const float*)d_in[11];
    const float* enc_mu_w    =(const float*)d_in[12];
    const float* enc_mu_b    =(const float*)d_in[13];
    const float* enc_sg_w    =(const float*)d_in[14];
    const float* enc_sg_b    =(const float*)d_in[15];
    const float* phi_z_w     =(const float*)d_in[16];
    const float* phi_z_b     =(const float*)d_in[17];
    const float* dec_h_w     =(const float*)d_in[18];
    const float* dec_h_b     =(const float*)d_in[19];
    const float* dec_mu_w    =(const float*)d_in[20];
    const float* dec_mu_b    =(const float*)d_in[21];
    const float* dec_sg_w    =(const float*)d_in[22];
    const float* dec_sg_b    =(const float*)d_in[23];
    const float* lstm_kernel =(const float*)d_in[24];
    const float* lstm_rec    =(const float*)d_in[25];
    const float* lstm_bias   =(const float*)d_in[26];
    float* out=(float*)d_out;

    float *pGx,*pEx,*pH,*pZ1,*pPH,*pDH,*pWgx,*pWex,*pGb,*pEb;
    cudaGetSymbolAddress((void**)&pGx, g_Gx);
    cudaGetSymbolAddress((void**)&pEx, g_Ex);
    cudaGetSymbolAddress((void**)&pH,  g_h);
    cudaGetSymbolAddress((void**)&pZ1, g_z1);
    cudaGetSymbolAddress((void**)&pPH, g_PH);
    cudaGetSymbolAddress((void**)&pDH, g_DH);
    cudaGetSymbolAddress((void**)&pWgx,g_Wgx);
    cudaGetSymbolAddress((void**)&pWex,g_Wex);
    cudaGetSymbolAddress((void**)&pGb, g_gb);
    cudaGetSymbolAddress((void**)&pEb, g_eb);

    // 1. fold biases
    bias_fold_k<<<9,128>>>(lstm_bias,lstm_kernel,enc_h_w,enc_h_b,phi_x_b);
    // 2. fused weights: W_gx = phi_x_w @ K_x ; W_ex = phi_x_w @ Wenc_x
    gemm_k<<<dim3(16,1),256>>>(phi_x_w,128,128, nullptr,0,0, lstm_kernel,1024, nullptr,0,
                               nullptr, pWgx,1024,0,0);
    gemm_k<<<dim3(2,1),256>>>(phi_x_w,128,128, nullptr,0,0, enc_h_w,128, nullptr,0,
                              nullptr, pWex,128,0,0);
    // 3. big input GEMMs (rows b*T+t)
    gemm_k<<<dim3(16,512),256>>>(x,128,128, nullptr,0,0, pWgx,1024, nullptr,0,
                                 pGb, pGx,1024,0,0);
    gemm_k<<<dim3(2,512),256>>>(x,128,128, nullptr,0,0, pWex,128, nullptr,0,
                                pEb, pEx,128,0,0);
    // 4. sequential recurrence
    seq_k<<<64,256>>>(eps, enc_h_w, enc_mu_w,enc_mu_b, enc_sg_w,enc_sg_b,
                      phi_z_w,phi_z_b, lstm_kernel, lstm_rec, out);
    // 5. prior epilogue (rows t*128+b)
    gemm_k<<<dim3(2,512),256>>>(pH,256,256, nullptr,0,0, prior_h_w,128, nullptr,0,
                                prior_h_b, pPH,128,1,0);
    gemm_k<<<dim3(2,512),256>>>(pPH,128,128, nullptr,0,0, prior_mu_w,128, nullptr,0,
                                prior_mu_b, out+OFF_PMU,128,0,1);
    gemm_k<<<dim3(2,512),256>>>(pPH,128,128, nullptr,0,0, prior_sg_w,128, nullptr,0,
                                prior_sg_b, out+OFF_PSG,128,2,1);
    // 6. dec epilogue: dec_in = [z1, h]
    gemm_k<<<dim3(2,512),256>>>(pZ1,128,128, pH,256,256, dec_h_w,128, dec_h_w+128*128,128,
                                dec_h_b, pDH,128,1,0);
    gemm_k<<<dim3(2,512),256>>>(pDH,128,128, nullptr,0,0, dec_mu_w,128, nullptr,0,
                                dec_mu_b, out+OFF_DMU,128,0,1);
    gemm_k<<<dim3(2,512),256>>>(pDH,128,128, nullptr,0,0, dec_sg_w,128, nullptr,0,
                                dec_sg_b, out+OFF_DSG,128,2,1);
}

// round 3
// speedup vs baseline: 4.6927x; 4.6927x over previous
#include <cuda_runtime.h>
#include <cooperative_groups.h>
#include <math.h>

namespace cg = cooperative_groups;

#define Tt 512
#define SEQSZ (128*512*128)
#define OFF_EMU 16384
#define OFF_ESG (OFF_EMU + 1*SEQSZ)
#define OFF_DMU (OFF_EMU + 2*SEQSZ)
#define OFF_DSG (OFF_EMU + 3*SEQSZ)
#define OFF_PMU (OFF_EMU + 4*SEQSZ)
#define OFF_PSG (OFF_EMU + 5*SEQSZ)

// scratch (static device globals; no runtime alloc)
__device__ float g_Gx[65536*1024];  // row b*T+t: x-contrib to gates (+biases folded)
__device__ float g_Ex[65536*128];   // row b*T+t: x-contrib to enc_h preact (+biases folded)
__device__ float g_h [65536*256];   // row t*128+b: h INPUT at step t
__device__ float g_z1[65536*128];   // row t*128+b
__device__ float g_PH[65536*128];
__device__ float g_DH[65536*128];
__device__ float g_Wgx[128*1024];
__device__ float g_Wex[128*128];
__device__ float g_gb[1024];
__device__ float g_eb[128];

__device__ __forceinline__ float softplus_(float x){ return fmaxf(x,0.f)+log1pf(expf(-fabsf(x))); }
__device__ __forceinline__ float sigmoid_(float x){ return 1.f/(1.f+expf(-x)); }

// ------------------------- tiled SGEMM (unchanged, passing) ----------------
__global__ __launch_bounds__(256) void gemm_k(
    const float* __restrict__ A1,int lda1,int K1,
    const float* __restrict__ A2,int lda2,int K2,
    const float* __restrict__ W1,int ldw1,
    const float* __restrict__ W2,int ldw2,
    const float* __restrict__ bias,
    float* __restrict__ out,int N,int act,int btmode)
{
    __shared__ __align__(16) float As[8][128];
    __shared__ __align__(16) float Ws[8][64];
    const int bm=blockIdx.y*128, bn=blockIdx.x*64;
    const int tid=threadIdx.x;
    const int ty=tid>>4, tx=tid&15;
    const int lr=tid>>1, lc=(tid&1)*4;
    const int wr=tid>>6, wc=tid&63;
    float acc[8][4];
    #pragma unroll
    for(int i=0;i<8;i++)
      #pragma unroll
      for(int j=0;j<4;j++) acc[i][j]=0.f;
    for(int seg=0;seg<2;seg++){
        const float* A = seg? A2:A1;
        if(A==nullptr) continue;
        const float* W = seg? W2:W1;
        const int lda=seg?lda2:lda1, ldw=seg?ldw2:ldw1, K=seg?K2:K1;
        for(int k0=0;k0<K;k0+=8){
            float4 av = *(const float4*)(A + (size_t)(bm+lr)*lda + k0+lc);
            float w0 = W[(size_t)(k0+wr)*ldw + bn+wc];
            float w1 = W[(size_t)(k0+wr+4)*ldw + bn+wc];
            __syncthreads();
            As[lc+0][lr]=av.x; As[lc+1][lr]=av.y; As[lc+2][lr]=av.z; As[lc+3][lr]=av.w;
            Ws[wr][wc]=w0; Ws[wr+4][wc]=w1;
            __syncthreads();
            #pragma unroll
            for(int kk=0;kk<8;kk++){
                float a[8],w[4];
                *(float4*)&a[0]=*(const float4*)&As[kk][ty*8];
                *(float4*)&a[4]=*(const float4*)&As[kk][ty*8+4];
                *(float4*)&w[0]=*(const float4*)&Ws[kk][tx*4];
                #pragma unroll
                for(int i=0;i<8;i++)
                  #pragma unroll
                  for(int j=0;j<4;j++) acc[i][j]=fmaf(a[i],w[j],acc[i][j]);
            }
        }
    }
    #pragma unroll
    for(int i=0;i<8;i++){
        int r=bm+ty*8+i;
        #pragma unroll
        for(int j=0;j<4;j++){
            int n=bn+tx*4+j;
            float v=acc[i][j];
            if(bias) v+=bias[n];
            if(act==1) v=fmaxf(v,0.f);
            else if(act==2) v=softplus_(v);
            size_t idx;
            if(btmode){ int b=r&127, t=r>>7; idx=((size_t)b*Tt+t)*(size_t)N+n; }
            else idx=(size_t)r*N+n;
            out[idx]=v;
        }
    }
}

__global__ void bias_fold_k(const float* __restrict__ lstm_bias,
                            const float* __restrict__ lstm_kernel,
                            const float* __restrict__ enc_h_w,
                            const float* __restrict__ enc_h_b,
                            const float* __restrict__ phi_x_b)
{
    int idx=blockIdx.x*blockDim.x+threadIdx.x;
    if(idx<1024){
        float s=lstm_bias[idx];
        for(int f=0;f<128;f++) s=fmaf(phi_x_b[f],lstm_kernel[f*1024+idx],s);
        g_gb[idx]=s;
    } else if(idx<1152){
        int j=idx-1024;
        float s=enc_h_b[j];
        for(int f=0;f<128;f++) s=fmaf(phi_x_b[f],enc_h_w[f*128+j],s);
        g_eb[j]=s;
    }
}

// ---------------- cluster-distributed sequential recurrence ----------------
// 16 clusters x 8 CTAs. Cluster c owns batch rows [c*8, c*8+8).
// CTA rank owns: h cols [rank*32,+32), enc/z cols [rank*16,+16),
// gate cols {g*256 + rank*32 + j : g in 0..4, j in 0..32} (local col c = g*32+j).
// All weights for owned columns live in SMEM; only the z-part of lstm_kernel
// streams from L2. State vectors exchanged via DSMEM pushes + cluster.sync.

// SMEM layout (float offsets)
#define S_R    0        // R_s[256][128]          32768
#define S_WE   32768    // Wenc_s[256][16]        4096
#define S_WMU  36864    // Wmu_s[128][16]         2048
#define S_WSG  38912    // Wsg_s[128][16]         2048
#define S_WPZ  40960    // Wpz_s[128][16]         2048
#define S_HT   43008    // hT[2][256][8]          4096 (double buffered)
#define S_ET   47104    // eT[128][8]             1024
#define S_ZT   48128    // zT[128][8]             1024
#define S_Z1T  49152    // z1T[128][8]            1024
#define S_GP   50176    // gpart[4][128][8]       4096
#define S_AP   54272    // apart[512]             512
#define S_BIAS 54784    // mu_b[16], sg_b[16], pz_b[16]
#define S_TOTF 54832
#define SEQ_SMEM_BYTES (S_TOTF*4)

__global__ void __cluster_dims__(8,1,1) __launch_bounds__(512,1) seq_clu(
    const float* __restrict__ eps,
    const float* __restrict__ enc_h_w,
    const float* __restrict__ enc_mu_w, const float* __restrict__ enc_mu_b,
    const float* __restrict__ enc_sg_w, const float* __restrict__ enc_sg_b,
    const float* __restrict__ phi_z_w,  const float* __restrict__ phi_z_b,
    const float* __restrict__ lstm_kernel, const float* __restrict__ lstm_rec,
    float* __restrict__ out)
{
    extern __shared__ __align__(16) float sm[];
    float* R_s    = sm + S_R;
    float* Wenc_s = sm + S_WE;
    float* Wmu_s  = sm + S_WMU;
    float* Wsg_s  = sm + S_WSG;
    float* Wpz_s  = sm + S_WPZ;
    float* hT     = sm + S_HT;     // [2][256*8]
    float* eT     = sm + S_ET;
    float* zT     = sm + S_ZT;
    float* z1T    = sm + S_Z1T;
    float* gp     = sm + S_GP;
    float* apart  = sm + S_AP;
    float* bias_s = sm + S_BIAS;

    cg::cluster_group clu = cg::this_cluster();
    const int tid  = threadIdx.x;
    const int rank = blockIdx.x & 7;
    const int cid  = blockIdx.x >> 3;

    // ---- load weight slices into SMEM ----
    for(int idx=tid; idx<256*128; idx+=512){
        int k=idx>>7, c=idx&127;
        int gcol=(c>>5)*256 + rank*32 + (c&31);
        R_s[idx] = lstm_rec[k*1024 + gcol];
    }
    for(int idx=tid; idx<256*16; idx+=512){
        int k=idx>>4, j=idx&15;
        Wenc_s[idx] = enc_h_w[(128+k)*128 + rank*16 + j];
    }
    for(int idx=tid; idx<128*16; idx+=512){
        int k=idx>>4, j=idx&15;
        Wmu_s[idx] = enc_mu_w[k*128 + rank*16 + j];
        Wsg_s[idx] = enc_sg_w[k*128 + rank*16 + j];
        Wpz_s[idx] = phi_z_w [k*128 + rank*16 + j];
    }
    if(tid<16){
        bias_s[tid]    = enc_mu_b[rank*16+tid];
        bias_s[16+tid] = enc_sg_b[rank*16+tid];
        bias_s[32+tid] = phi_z_b [rank*16+tid];
    }
    for(int idx=tid; idx<2*256*8; idx+=512) hT[idx]=0.f;
    __syncthreads();
    clu.sync();

    float c_st = 0.f;  // cell state for tid<256: (row=tid>>5, hcol j=tid&31)

    const int dcol = tid & 127, dseg = tid >> 7;
    const int dgb = dcol >> 5, dwj = dcol & 31;
    const int dgcol = dgb*256 + rank*32 + dwj;
    const float* Kzp = lstm_kernel + (size_t)128*1024 + dgcol;

    for(int t=0; t<Tt; t++){
        const int cur = t & 1, nxt = cur ^ 1;
        float* hTc = hT + cur*2048;
        float* hTn = hT + nxt*2048;

        // ---- early global loads (hide DRAM behind phases a-c) ----
        float exv=0.f, epsv=0.f, gxv[8];
        if(tid<128){
            int r=tid>>4, c=tid&15;
            size_t base = ((size_t)(cid*8+r)*Tt + t)*128 + rank*16 + c;
            exv  = g_Ex[base];
            epsv = eps [base];
            #pragma unroll
            for(int r8=0;r8<8;r8++)
                gxv[r8] = g_Gx[((size_t)(cid*8+r8)*Tt + t)*1024 + dgcol];
        }
        // store h input for prior/dec epilogues
        if(tid<256){
            int row=tid>>5, j=tid&31;
            g_h[((size_t)t*128 + cid*8 + row)*256 + rank*32 + j] = hTc[(rank*32+j)*8 + row];
        }

        // ---- (a) enc_h slice: relu(Ex + h @ Wenc_h) ----
        {
            int oc=tid&127, seg=tid>>7, row=oc>>4, col=oc&15;
            float s=0.f;
            int k0=seg*64;
            #pragma unroll 4
            for(int k=k0;k<k0+64;k++)
                s = fmaf(hTc[k*8+row], Wenc_s[k*16+col], s);
            apart[tid]=s;
        }
        __syncthreads();
        if(tid<128){
            int row=tid>>4, col=tid&15;
            float v = apart[tid]+apart[tid+128]+apart[tid+256]+apart[tid+384] + exv;
            v = fmaxf(v,0.f);
            float* lp = &eT[(rank*16+col)*8 + row];
            #pragma unroll
            for(int rk=0;rk<8;rk++) *(float*)clu.map_shared_rank((void*)lp, rk) = v;
        }
        clu.sync();  // B1

        // ---- (b) enc_mu / enc_sigma / z ----
        {
            int o=tid&255, seg=tid>>8, row=o>>5, col=(o>>1)&15, typ=o&1;
            const float* W = typ ? Wsg_s : Wmu_s;
            float s=0.f;
            int k0=seg*64;
            #pragma unroll 4
            for(int k=k0;k<k0+64;k++)
                s = fmaf(eT[k*8+row], W[k*16+col], s);
            apart[tid]=s;
        }
        __syncthreads();
        if(tid<128){
            int row=tid>>4, col=tid&15;
            int o0=(row<<5)+(col<<1);
            float mu = apart[o0]   + apart[o0+256]   + bias_s[col];
            float sg = softplus_(apart[o0+1] + apart[o0+1+256] + bias_s[16+col]);
            size_t base = ((size_t)(cid*8+row)*Tt + t)*128 + rank*16 + col;
            out[OFF_EMU+base]=mu; out[OFF_ESG+base]=sg;
            float z = fmaf(sg, epsv, mu);
            float* lp = &zT[(rank*16+col)*8 + row];
            #pragma unroll
            for(int rk=0;rk<8;rk++) *(float*)clu.map_shared_rank((void*)lp, rk) = z;
        }
        clu.sync();  // B2

        // ---- (c) z1 = relu(z @ phi_z_w + b) ----
        {
            int oc=tid&127, seg=tid>>7, row=oc>>4, col=oc&15;
            float s=0.f;
            int k0=seg*32;
            #pragma unroll 4
            for(int k=k0;k<k0+32;k++)
                s = fmaf(zT[k*8+row], Wpz_s[k*16+col], s);
            apart[tid]=s;
        }
        __syncthreads();
        if(tid<128){
            int row=tid>>4, col=tid&15;
            float v = apart[tid]+apart[tid+128]+apart[tid+256]+apart[tid+384] + bias_s[32+col];
            v = fmaxf(v,0.f);
            g_z1[((size_t)t*128 + cid*8 + row)*128 + rank*16 + col] = v;
            if(t==Tt-1) out[(size_t)(cid*8+row)*128 + rank*16 + col] = v;
            float* lp = &z1T[(rank*16+col)*8 + row];
            #pragma unroll
            for(int rk=0;rk<8;rk++) *(float*)clu.map_shared_rank((void*)lp, rk) = v;
        }
        clu.sync();  // B3

        // ---- (d) gates (k-split over 384) + LSTM cell ----
        {
            float acc[8];
            if(dseg==0){
                #pragma unroll
                for(int r=0;r<8;r++) acc[r]=gxv[r];
            } else {
                #pragma unroll
                for(int r=0;r<8;r++) acc[r]=0.f;
            }
            int k0=dseg*96, k1=k0+96;
            int kz_hi = (k1<128)? k1 : 128;
            #pragma unroll 4
            for(int k=k0;k<kz_hi;k++){
                float w = __ldg(Kzp + (size_t)k*1024);
                float4 a0=*(const float4*)&z1T[k*8];
                float4 a1=*(const float4*)&z1T[k*8+4];
                acc[0]=fmaf(w,a0.x,acc[0]); acc[1]=fmaf(w,a0.y,acc[1]);
                acc[2]=fmaf(w,a0.z,acc[2]); acc[3]=fmaf(w,a0.w,acc[3]);
                acc[4]=fmaf(w,a1.x,acc[4]); acc[5]=fmaf(w,a1.y,acc[5]);
                acc[6]=fmaf(w,a1.z,acc[6]); acc[7]=fmaf(w,a1.w,acc[7]);
            }
            if(k1>128){
                int kr0 = (k0>128)? k0-128 : 0;
                int kr1 = k1-128;
                #pragma unroll 4
                for(int kk=kr0;kk<kr1;kk++){
                    float w = R_s[kk*128+dcol];
                    float4 a0=*(const float4*)&hTc[kk*8];
                    float4 a1=*(const float4*)&hTc[kk*8+4];
                    acc[0]=fmaf(w,a0.x,acc[0]); acc[1]=fmaf(w,a0.y,acc[1]);
                    acc[2]=fmaf(w,a0.z,acc[2]); acc[3]=fmaf(w,a0.w,acc[3]);
                    acc[4]=fmaf(w,a1.x,acc[4]); acc[5]=fmaf(w,a1.y,acc[5]);
                    acc[6]=fmaf(w,a1.z,acc[6]); acc[7]=fmaf(w,a1.w,acc[7]);
                }
            }
            *(float4*)&gp[dseg*1024 + dcol*8]   = make_float4(acc[0],acc[1],acc[2],acc[3]);
            *(float4*)&gp[dseg*1024 + dcol*8+4] = make_float4(acc[4],acc[5],acc[6],acc[7]);
        }
        __syncthreads();
        if(tid<256){
            int row=tid>>5, j=tid&31;
            float gi=0,gf=0,gg=0,go=0;
            #pragma unroll
            for(int s=0;s<4;s++){
                gi += gp[s*1024 + (     j)*8 + row];
                gf += gp[s*1024 + (32 + j)*8 + row];
                gg += gp[s*1024 + (64 + j)*8 + row];
                go += gp[s*1024 + (96 + j)*8 + row];
            }
            float iv=sigmoid_(gi), fv=sigmoid_(gf), gv=tanhf(gg), ov=sigmoid_(go);
            c_st = fv*c_st + iv*gv;
            float hv = ov*tanhf(c_st);
            float* lp = &hTn[(rank*32+j)*8 + row];
            #pragma unroll
            for(int rk=0;rk<8;rk++) *(float*)clu.map_shared_rank((void*)lp, rk) = hv;
        }
        clu.sync();  // B4 (end of step)
    }
}

extern "C" void kernel_launch(void* const* d_in, const int* in_sizes, int n_in,
                              void* d_out, int out_size)
{
    (void)in_sizes;(void)n_in;(void)out_size;
    const float* x           =(const float*)d_in[0];
    const float* eps         =(const float*)d_in[1];
    const float* prior_h_w   =(const float*)d_in[2];
    const float* prior_h_b   =(const float*)d_in[3];
    const float* prior_mu_w  =(const float*)d_in[4];
    const float* prior_mu_b  =(const float*)d_in[5];
    const float* prior_sg_w  =(const float*)d_in[6];
    const float* prior_sg_b  =(const float*)d_in[7];
    const float* phi_x_w     =(const float*)d_in[8];
    const float* phi_x_b     =(const float*)d_in[9];
    const float* enc_h_w     =(const float*)d_in[10];
    const float* enc_h_b     =(const float*)d_in[11];
    const float* enc_mu_w    =(const float*)d_in[12];
    const float* enc_mu_b    =(const float*)d_in[13];
    const float* enc_sg_w    =(const float*)d_in[14];
    const float* enc_sg_b    =(const float*)d_in[15];
    const float* phi_z_w     =(const float*)d_in[16];
    const float* phi_z_b     =(const float*)d_in[17];
    const float* dec_h_w     =(const float*)d_in[18];
    const float* dec_h_b     =(const float*)d_in[19];
    const float* dec_mu_w    =(const float*)d_in[20];
    const float* dec_mu_b    =(const float*)d_in[21];
    const float* dec_sg_w    =(const float*)d_in[22];
    const float* dec_sg_b    =(const float*)d_in[23];
    const float* lstm_kernel =(const float*)d_in[24];
    const float* lstm_rec    =(const float*)d_in[25];
    const float* lstm_bias   =(const float*)d_in[26];
    float* out=(float*)d_out;

    float *pGx,*pEx,*pH,*pZ1,*pPH,*pDH,*pWgx,*pWex,*pGb,*pEb;
    cudaGetSymbolAddress((void**)&pGx, g_Gx);
    cudaGetSymbolAddress((void**)&pEx, g_Ex);
    cudaGetSymbolAddress((void**)&pH,  g_h);
    cudaGetSymbolAddress((void**)&pZ1, g_z1);
    cudaGetSymbolAddress((void**)&pPH, g_PH);
    cudaGetSymbolAddress((void**)&pDH, g_DH);
    cudaGetSymbolAddress((void**)&pWgx,g_Wgx);
    cudaGetSymbolAddress((void**)&pWex,g_Wex);
    cudaGetSymbolAddress((void**)&pGb, g_gb);
    cudaGetSymbolAddress((void**)&pEb, g_eb);

    cudaFuncSetAttribute(seq_clu, cudaFuncAttributeMaxDynamicSharedMemorySize, SEQ_SMEM_BYTES);

    // 1. fold biases
    bias_fold_k<<<9,128>>>(lstm_bias,lstm_kernel,enc_h_w,enc_h_b,phi_x_b);
    // 2. fused weights: W_gx = phi_x_w @ K_x ; W_ex = phi_x_w @ Wenc_x
    gemm_k<<<dim3(16,1),256>>>(phi_x_w,128,128, nullptr,0,0, lstm_kernel,1024, nullptr,0,
                               nullptr, pWgx,1024,0,0);
    gemm_k<<<dim3(2,1),256>>>(phi_x_w,128,128, nullptr,0,0, enc_h_w,128, nullptr,0,
                              nullptr, pWex,128,0,0);
    // 3. big input GEMMs (rows b*T+t)
    gemm_k<<<dim3(16,512),256>>>(x,128,128, nullptr,0,0, pWgx,1024, nullptr,0,
                                 pGb, pGx,1024,0,0);
    gemm_k<<<dim3(2,512),256>>>(x,128,128, nullptr,0,0, pWex,128, nullptr,0,
                                pEb, pEx,128,0,0);
    // 4. sequential recurrence (16 clusters x 8 CTAs, SMEM-resident weights)
    seq_clu<<<128,512,SEQ_SMEM_BYTES>>>(eps, enc_h_w, enc_mu_w,enc_mu_b, enc_sg_w,enc_sg_b,
                                        phi_z_w,phi_z_b, lstm_kernel, lstm_rec, out);
    // 5. prior epilogue (rows t*128+b)
    gemm_k<<<dim3(2,512),256>>>(pH,256,256, nullptr,0,0, prior_h_w,128, nullptr,0,
                                prior_h_b, pPH,128,1,0);
    gemm_k<<<dim3(2,512),256>>>(pPH,128,128, nullptr,0,0, prior_mu_w,128, nullptr,0,
                                prior_mu_b, out+OFF_PMU,128,0,1);
    gemm_k<<<dim3(2,512),256>>>(pPH,128,128, nullptr,0,0, prior_sg_w,128, nullptr,0,
                                prior_sg_b, out+OFF_PSG,128,2,1);
    // 6. dec epilogue: dec_in = [z1, h]
    gemm_k<<<dim3(2,512),256>>>(pZ1,128,128, pH,256,256, dec_h_w,128, dec_h_w+128*128,128,
                                dec_h_b, pDH,128,1,0);
    gemm_k<<<dim3(2,512),256>>>(pDH,128,128, nullptr,0,0, dec_mu_w,128, nullptr,0,
                                dec_mu_b, out+OFF_DMU,128,0,1);
    gemm_k<<<dim3(2,512),256>>>(pDH,128,128, nullptr,0,0, dec_sg_w,128, nullptr,0,
                                dec_sg_b, out+OFF_DSG,128,2,1);
}

// round 5
// speedup vs baseline: 5.2441x; 1.1175x over previous
#include <cuda_runtime.h>
#include <stdint.h>
#include <math.h>

#define Tt 512
#define SEQSZ (128*512*128)
#define OFF_EMU 16384
#define OFF_ESG (OFF_EMU + 1*SEQSZ)
#define OFF_DMU (OFF_EMU + 2*SEQSZ)
#define OFF_DSG (OFF_EMU + 3*SEQSZ)
#define OFF_PMU (OFF_EMU + 4*SEQSZ)
#define OFF_PSG (OFF_EMU + 5*SEQSZ)

// scratch (static device globals; no runtime alloc)
__device__ float g_Gx[65536*1024];  // row b*T+t: x-contrib to gates (+biases folded)
__device__ float g_Ex[65536*128];   // row b*T+t: x-contrib to enc_h preact (+biases folded)
__device__ float g_h [65536*256];   // row t*128+b: h INPUT at step t
__device__ float g_z1[65536*128];   // row t*128+b
__device__ float g_PH[65536*128];
__device__ float g_DH[65536*128];
__device__ float g_Wgx[128*1024];
__device__ float g_Wex[128*128];
__device__ float g_KzT[1024*128];   // KzT[col][k] = lstm_kernel[128+k][col]
__device__ float g_gb[1024];
__device__ float g_eb[128];

typedef unsigned long long ull;

__device__ __forceinline__ float softplus_(float x){ return fmaxf(x,0.f)+log1pf(expf(-fabsf(x))); }
__device__ __forceinline__ float sigmoid_(float x){ return 1.f/(1.f+expf(-x)); }

__device__ __forceinline__ ull pack2_(float v){
    ull r; asm("mov.b64 %0, {%1, %1};" : "=l"(r) : "f"(v)); return r;
}
__device__ __forceinline__ void ffma2_(ull &d, ull a, ull b){
    asm("fma.rn.f32x2 %0, %1, %2, %0;" : "+l"(d) : "l"(a), "l"(b));
}
__device__ __forceinline__ void unpack2_(ull v, float &lo, float &hi){
    asm("mov.b64 {%0, %1}, %2;" : "=f"(lo), "=f"(hi) : "l"(v));
}
__device__ __forceinline__ unsigned mapa_(unsigned addr, unsigned rank){
    unsigned r; asm("mapa.shared::cluster.u32 %0, %1, %2;" : "=r"(r) : "r"(addr), "r"(rank));
    return r;
}
__device__ __forceinline__ void st_async_(unsigned daddr, unsigned mbar, float v){
    asm volatile("st.async.weak.shared::cluster.mbarrier::complete_tx::bytes.b32 [%0], %1, [%2];"
        :: "r"(daddr), "r"(__float_as_uint(v)), "r"(mbar) : "memory");
}
__device__ __forceinline__ void mbar_init_(unsigned mbar, unsigned cnt){
    asm volatile("mbarrier.init.shared.b64 [%0], %1;" :: "r"(mbar), "r"(cnt) : "memory");
}
__device__ __forceinline__ void mbar_expect_(unsigned mbar, unsigned bytes){
    asm volatile("mbarrier.arrive.expect_tx.shared.b64 _, [%0], %1;" :: "r"(mbar), "r"(bytes) : "memory");
}
__device__ __forceinline__ void mbar_wait_(unsigned mbar, unsigned parity){
    unsigned done;
    asm volatile("{\n\t.reg .pred p;\n\t"
        "mbarrier.try_wait.parity.acquire.cta.shared::cta.b64 p, [%1], %2;\n\t"
        "selp.b32 %0, 1, 0, p;\n\t}"
        : "=r"(done) : "r"(mbar), "r"(parity) : "memory");
    while(!done){
        asm volatile("{\n\t.reg .pred p;\n\t"
            "mbarrier.try_wait.parity.acquire.cta.shared::cta.b64 p, [%1], %2, 0x989680;\n\t"
            "selp.b32 %0, 1, 0, p;\n\t}"
            : "=r"(done) : "r"(mbar), "r"(parity) : "memory");
    }
}
#define CLUSTER_SYNC_() do{ \
    asm volatile("barrier.cluster.arrive.aligned;" ::: "memory"); \
    asm volatile("barrier.cluster.wait.aligned;" ::: "memory"); }while(0)

// ------------------------- tiled SGEMM (unchanged, passing) ----------------
__global__ __launch_bounds__(256) void gemm_k(
    const float* __restrict__ A1,int lda1,int K1,
    const float* __restrict__ A2,int lda2,int K2,
    const float* __restrict__ W1,int ldw1,
    const float* __restrict__ W2,int ldw2,
    const float* __restrict__ bias,
    float* __restrict__ out,int N,int act,int btmode)
{
    __shared__ __align__(16) float As[8][128];
    __shared__ __align__(16) float Ws[8][64];
    const int bm=blockIdx.y*128, bn=blockIdx.x*64;
    const int tid=threadIdx.x;
    const int ty=tid>>4, tx=tid&15;
    const int lr=tid>>1, lc=(tid&1)*4;
    const int wr=tid>>6, wc=tid&63;
    float acc[8][4];
    #pragma unroll
    for(int i=0;i<8;i++)
      #pragma unroll
      for(int j=0;j<4;j++) acc[i][j]=0.f;
    for(int seg=0;seg<2;seg++){
        const float* A = seg? A2:A1;
        if(A==nullptr) continue;
        const float* W = seg? W2:W1;
        const int lda=seg?lda2:lda1, ldw=seg?ldw2:ldw1, K=seg?K2:K1;
        for(int k0=0;k0<K;k0+=8){
            float4 av = *(const float4*)(A + (size_t)(bm+lr)*lda + k0+lc);
            float w0 = W[(size_t)(k0+wr)*ldw + bn+wc];
            float w1 = W[(size_t)(k0+wr+4)*ldw + bn+wc];
            __syncthreads();
            As[lc+0][lr]=av.x; As[lc+1][lr]=av.y; As[lc+2][lr]=av.z; As[lc+3][lr]=av.w;
            Ws[wr][wc]=w0; Ws[wr+4][wc]=w1;
            __syncthreads();
            #pragma unroll
            for(int kk=0;kk<8;kk++){
                float a[8],w[4];
                *(float4*)&a[0]=*(const float4*)&As[kk][ty*8];
                *(float4*)&a[4]=*(const float4*)&As[kk][ty*8+4];
                *(float4*)&w[0]=*(const float4*)&Ws[kk][tx*4];
                #pragma unroll
                for(int i=0;i<8;i++)
                  #pragma unroll
                  for(int j=0;j<4;j++) acc[i][j]=fmaf(a[i],w[j],acc[i][j]);
            }
        }
    }
    #pragma unroll
    for(int i=0;i<8;i++){
        int r=bm+ty*8+i;
        #pragma unroll
        for(int j=0;j<4;j++){
            int n=bn+tx*4+j;
            float v=acc[i][j];
            if(bias) v+=bias[n];
            if(act==1) v=fmaxf(v,0.f);
            else if(act==2) v=softplus_(v);
            size_t idx;
            if(btmode){ int b=r&127, t=r>>7; idx=((size_t)b*Tt+t)*(size_t)N+n; }
            else idx=(size_t)r*N+n;
            out[idx]=v;
        }
    }
}

__global__ void bias_fold_k(const float* __restrict__ lstm_bias,
                            const float* __restrict__ lstm_kernel,
                            const float* __restrict__ enc_h_w,
                            const float* __restrict__ enc_h_b,
                            const float* __restrict__ phi_x_b)
{
    int idx=blockIdx.x*blockDim.x+threadIdx.x;
    if(idx<1024){
        float s=lstm_bias[idx];
        for(int f=0;f<128;f++) s=fmaf(phi_x_b[f],lstm_kernel[f*1024+idx],s);
        g_gb[idx]=s;
    } else if(idx<1152){
        int j=idx-1024;
        float s=enc_h_b[j];
        for(int f=0;f<128;f++) s=fmaf(phi_x_b[f],enc_h_w[f*128+j],s);
        g_eb[j]=s;
    }
}

__global__ void kz_transpose_k(const float* __restrict__ lstm_kernel){
    int k=blockIdx.x; // 0..127
    for(int c=threadIdx.x;c<1024;c+=256)
        g_KzT[(size_t)c*128+k]=lstm_kernel[(size_t)(128+k)*1024+c];
}

// ---------------- cluster-distributed sequential recurrence ----------------
// 16 clusters x 8 CTAs. Cluster c owns batch rows [c*8, c*8+8).
// CTA rank owns: enc/z/z1 cols [rank*16,+16), h cols [rank*32,+32),
// gate cols {g*256 + rank*32 + j}. Weights in SMEM; KzT chunk prefetched to
// registers each step. Exchanges via st.async + per-phase mbarrier tx.

// SMEM layout (float offsets)
#define S_R    0        // R_s[256][128]
#define S_WE   32768    // Wenc_s[256][16]
#define S_WMU  36864
#define S_WSG  38912
#define S_WPZ  40960
#define S_HT   43008    // hT[2][256][8] double buffered
#define S_ET   47104    // eT[128][8]
#define S_ZT   48128
#define S_Z1T  49152
#define S_GP   50176    // gp[4][8][128]
#define S_AP   54272    // phase-a partials [512]
#define S_AP2  54784    // phase-b partials [512]
#define S_AP3  55296    // phase-c partials [512]
#define S_BIAS 55808    // mu_b[16], sg_b[16], pz_b[16]
#define S_MB   55856    // 4 mbarriers (8 ull slots)
#define S_TOTF 55872
#define SEQ_SMEM_BYTES (S_TOTF*4)

__global__ void __cluster_dims__(8,1,1) __launch_bounds__(512,1) seq_clu(
    const float* __restrict__ eps,
    const float* __restrict__ enc_h_w,
    const float* __restrict__ enc_mu_w, const float* __restrict__ enc_mu_b,
    const float* __restrict__ enc_sg_w, const float* __restrict__ enc_sg_b,
    const float* __restrict__ phi_z_w,  const float* __restrict__ phi_z_b,
    const float* __restrict__ lstm_kernel, const float* __restrict__ lstm_rec,
    float* __restrict__ out)
{
    extern __shared__ __align__(16) float sm[];
    float* R_s    = sm + S_R;
    float* Wenc_s = sm + S_WE;
    float* Wmu_s  = sm + S_WMU;
    float* Wsg_s  = sm + S_WSG;
    float* Wpz_s  = sm + S_WPZ;
    float* hT     = sm + S_HT;
    float* eT     = sm + S_ET;
    float* zT     = sm + S_ZT;
    float* z1T    = sm + S_Z1T;
    float* gp     = sm + S_GP;
    float* apA    = sm + S_AP;
    float* apB    = sm + S_AP2;
    float* apC    = sm + S_AP3;
    float* bias_s = sm + S_BIAS;

    const unsigned smb = (unsigned)__cvta_generic_to_shared(sm);
    const unsigned mbE  = smb + S_MB*4;
    const unsigned mbZ  = mbE + 8;
    const unsigned mbZ1 = mbE + 16;
    const unsigned mbH  = mbE + 24;

    const int tid  = threadIdx.x;
    const int rank = blockIdx.x & 7;
    const int cid  = blockIdx.x >> 3;

    // ---- load weight slices into SMEM ----
    for(int idx=tid; idx<256*128; idx+=512){
        int k=idx>>7, c=idx&127;
        int gcol=(c>>5)*256 + rank*32 + (c&31);
        R_s[idx] = lstm_rec[k*1024 + gcol];
    }
    for(int idx=tid; idx<256*16; idx+=512){
        int k=idx>>4, j=idx&15;
        Wenc_s[idx] = enc_h_w[(128+k)*128 + rank*16 + j];
    }
    for(int idx=tid; idx<128*16; idx+=512){
        int k=idx>>4, j=idx&15;
        Wmu_s[idx] = enc_mu_w[k*128 + rank*16 + j];
        Wsg_s[idx] = enc_sg_w[k*128 + rank*16 + j];
        Wpz_s[idx] = phi_z_w [k*128 + rank*16 + j];
    }
    if(tid<16){
        bias_s[tid]    = enc_mu_b[rank*16+tid];
        bias_s[16+tid] = enc_sg_b[rank*16+tid];
        bias_s[32+tid] = phi_z_b [rank*16+tid];
    }
    for(int idx=tid; idx<2*256*8; idx+=512) hT[idx]=0.f;
    if(tid==0){
        mbar_init_(mbE,1); mbar_init_(mbZ,1); mbar_init_(mbZ1,1); mbar_init_(mbH,1);
    }
    __syncthreads();
    CLUSTER_SYNC_();

    float c_st = 0.f;  // cell state for tid<256: (row=tid>>5, j=tid&31)

    const int dcol = tid & 127, dseg = tid >> 7;
    const int dgcol = (dcol>>5)*256 + rank*32 + (dcol&31);

    for(int t=0; t<Tt; t++){
        const unsigned par = t & 1;
        float* hTc = hT + (t&1)*2048;
        const unsigned hTn_off = (unsigned)(S_HT + ((t+1)&1)*2048);

        if(tid==0){
            mbar_expect_(mbE,4096); mbar_expect_(mbZ,4096);
            mbar_expect_(mbZ1,4096); mbar_expect_(mbH,8192);
        }

        // ---- prefetches (hidden behind phases a-c) ----
        float exv=0.f, epsv=0.f;
        if(tid<128){
            int r=tid>>4, c=tid&15;
            size_t base = ((size_t)(cid*8+r)*Tt + t)*128 + rank*16 + c;
            exv  = g_Ex[base];
            epsv = eps [base];
        }
        float gxv4[4];
        if(tid<256){
            int row=tid>>5, j=tid&31;
            size_t gb = ((size_t)(cid*8+row)*Tt + t)*1024 + rank*32 + j;
            #pragma unroll
            for(int g=0;g<4;g++) gxv4[g]=g_Gx[gb + (size_t)g*256];
        }
        float w32[32];
        {
            const float4* kp = (const float4*)(g_KzT + (size_t)dgcol*128 + dseg*32);
            #pragma unroll
            for(int u=0;u<8;u++) *(float4*)&w32[u*4] = __ldg(&kp[u]);
        }
        // store h input for prior/dec epilogues
        if(tid<256){
            int row=tid>>5, j=tid&31;
            g_h[((size_t)t*128 + cid*8 + row)*256 + rank*32 + j] = hTc[(rank*32+j)*8 + row];
        }

        // ---- (a) enc_h slice: relu(Ex + h @ Wenc_h) ----
        {
            int oc=tid&127, seg=tid>>7, row=oc>>4, col=oc&15;
            float s0=0.f, s1=0.f;
            int k0=seg*64;
            #pragma unroll 4
            for(int k=k0;k<k0+64;k+=2){
                s0 = fmaf(hTc[k*8+row],     Wenc_s[k*16+col],     s0);
                s1 = fmaf(hTc[(k+1)*8+row], Wenc_s[(k+1)*16+col], s1);
            }
            apA[tid]=s0+s1;
        }
        __syncthreads();
        if(tid<128){
            int row=tid>>4, col=tid&15;
            float v = apA[tid]+apA[tid+128]+apA[tid+256]+apA[tid+384] + exv;
            v = fmaxf(v,0.f);
            unsigned la = smb + (unsigned)(S_ET + (rank*16+col)*8 + row)*4u;
            #pragma unroll
            for(unsigned rk=0;rk<8;rk++) st_async_(mapa_(la,rk), mapa_(mbE,rk), v);
        }
        mbar_wait_(mbE, par);

        // ---- (b) enc_mu / enc_sigma / z ----
        {
            int o=tid&255, seg=tid>>8, row=o>>5, col=(o>>1)&15, typ=o&1;
            const float* W = typ ? Wsg_s : Wmu_s;
            float s0=0.f, s1=0.f;
            int k0=seg*64;
            #pragma unroll 4
            for(int k=k0;k<k0+64;k+=2){
                s0 = fmaf(eT[k*8+row],     W[k*16+col],     s0);
                s1 = fmaf(eT[(k+1)*8+row], W[(k+1)*16+col], s1);
            }
            apB[tid]=s0+s1;
        }
        __syncthreads();
        if(tid<128){
            int row=tid>>4, col=tid&15;
            int o0=(row<<5)+(col<<1);
            float mu = apB[o0]   + apB[o0+256]   + bias_s[col];
            float sg = softplus_(apB[o0+1] + apB[o0+1+256] + bias_s[16+col]);
            size_t base = ((size_t)(cid*8+row)*Tt + t)*128 + rank*16 + col;
            out[OFF_EMU+base]=mu; out[OFF_ESG+base]=sg;
            float z = fmaf(sg, epsv, mu);
            unsigned la = smb + (unsigned)(S_ZT + (rank*16+col)*8 + row)*4u;
            #pragma unroll
            for(unsigned rk=0;rk<8;rk++) st_async_(mapa_(la,rk), mapa_(mbZ,rk), z);
        }
        mbar_wait_(mbZ, par);

        // ---- (c) z1 = relu(z @ phi_z_w + b) ----
        {
            int oc=tid&127, seg=tid>>7, row=oc>>4, col=oc&15;
            float s0=0.f, s1=0.f;
            int k0=seg*32;
            #pragma unroll 4
            for(int k=k0;k<k0+32;k+=2){
                s0 = fmaf(zT[k*8+row],     Wpz_s[k*16+col],     s0);
                s1 = fmaf(zT[(k+1)*8+row], Wpz_s[(k+1)*16+col], s1);
            }
            apC[tid]=s0+s1;
        }
        __syncthreads();
        if(tid<128){
            int row=tid>>4, col=tid&15;
            float v = apC[tid]+apC[tid+128]+apC[tid+256]+apC[tid+384] + bias_s[32+col];
            v = fmaxf(v,0.f);
            g_z1[((size_t)t*128 + cid*8 + row)*128 + rank*16 + col] = v;
            if(t==Tt-1) out[(size_t)(cid*8+row)*128 + rank*16 + col] = v;
            unsigned la = smb + (unsigned)(S_Z1T + (rank*16+col)*8 + row)*4u;
            #pragma unroll
            for(unsigned rk=0;rk<8;rk++) st_async_(mapa_(la,rk), mapa_(mbZ1,rk), v);
        }
        mbar_wait_(mbZ1, par);

        // ---- (d) gates: z1@Kz (regs) + h@R (SMEM), f32x2 over row pairs ----
        {
            ull a0=0ull,a1=0ull,a2=0ull,a3=0ull;
            const int kz0=dseg*32;
            #pragma unroll
            for(int u=0;u<32;u++){
                ull w2 = pack2_(w32[u]);
                const ulonglong2* zp = (const ulonglong2*)(z1T + (kz0+u)*8);
                ulonglong2 p0 = zp[0], p1 = zp[1];
                ffma2_(a0,w2,p0.x); ffma2_(a1,w2,p0.y);
                ffma2_(a2,w2,p1.x); ffma2_(a3,w2,p1.y);
            }
            const int kr0=dseg*64;
            #pragma unroll 4
            for(int kk=kr0;kk<kr0+64;kk++){
                ull w2 = pack2_(R_s[kk*128+dcol]);
                const ulonglong2* hp = (const ulonglong2*)(hTc + kk*8);
                ulonglong2 p0 = hp[0], p1 = hp[1];
                ffma2_(a0,w2,p0.x); ffma2_(a1,w2,p0.y);
                ffma2_(a2,w2,p1.x); ffma2_(a3,w2,p1.y);
            }
            float r0,r1,r2,r3,r4,r5,r6,r7;
            unpack2_(a0,r0,r1); unpack2_(a1,r2,r3);
            unpack2_(a2,r4,r5); unpack2_(a3,r6,r7);
            float* gpp = gp + dseg*1024 + dcol;
            gpp[0*128]=r0; gpp[1*128]=r1; gpp[2*128]=r2; gpp[3*128]=r3;
            gpp[4*128]=r4; gpp[5*128]=r5; gpp[6*128]=r6; gpp[7*128]=r7;
        }
        __syncthreads();
        if(tid<256){
            int row=tid>>5, j=tid&31;
            float gi=gxv4[0], gf=gxv4[1], gg=gxv4[2], go=gxv4[3];
            #pragma unroll
            for(int s=0;s<4;s++){
                const float* gpp = gp + s*1024 + row*128;
                gi += gpp[j]; gf += gpp[32+j]; gg += gpp[64+j]; go += gpp[96+j];
            }
            float iv=sigmoid_(gi), fv=sigmoid_(gf), gv=tanhf(gg), ov=sigmoid_(go);
            c_st = fv*c_st + iv*gv;
            float hv = ov*tanhf(c_st);
            unsigned la = smb + (hTn_off + (unsigned)((rank*32+j)*8 + row))*4u;
            #pragma unroll
            for(unsigned rk=0;rk<8;rk++) st_async_(mapa_(la,rk), mapa_(mbH,rk), hv);
        }
        mbar_wait_(mbH, par);
    }
    CLUSTER_SYNC_();
}

extern "C" void kernel_launch(void* const* d_in, const int* in_sizes, int n_in,
                              void* d_out, int out_size)
{
    (void)in_sizes;(void)n_in;(void)out_size;
    const float* x           =(const float*)d_in[0];
    const float* eps         =(const float*)d_in[1];
    const float* prior_h_w   =(const float*)d_in[2];
    const float* prior_h_b   =(const float*)d_in[3];
    const float* prior_mu_w  =(const float*)d_in[4];
    const float* prior_mu_b  =(const float*)d_in[5];
    const float* prior_sg_w  =(const float*)d_in[6];
    const float* prior_sg_b  =(const float*)d_in[7];
    const float* phi_x_w     =(const float*)d_in[8];
    const float* phi_x_b     =(const float*)d_in[9];
    const float* enc_h_w     =(const float*)d_in[10];
    const float* enc_h_b     =(const float*)d_in[11];
    const float* enc_mu_w    =(const float*)d_in[12];
    const float* enc_mu_b    =(const float*)d_in[13];
    const float* enc_sg_w    =(const float*)d_in[14];
    const float* enc_sg_b    =(const float*)d_in[15];
    const float* phi_z_w     =(const float*)d_in[16];
    const float* phi_z_b     =(const float*)d_in[17];
    const float* dec_h_w     =(const float*)d_in[18];
    const float* dec_h_b     =(const float*)d_in[19];
    const float* dec_mu_w    =(const float*)d_in[20];
    const float* dec_mu_b    =(const float*)d_in[21];
    const float* dec_sg_w    =(const float*)d_in[22];
    const float* dec_sg_b    =(const float*)d_in[23];
    const float* lstm_kernel =(const float*)d_in[24];
    const float* lstm_rec    =(const float*)d_in[25];
    const float* lstm_bias   =(const float*)d_in[26];
    float* out=(float*)d_out;

    float *pGx,*pEx,*pH,*pZ1,*pPH,*pDH,*pWgx,*pWex,*pGb,*pEb;
    cudaGetSymbolAddress((void**)&pGx, g_Gx);
    cudaGetSymbolAddress((void**)&pEx, g_Ex);
    cudaGetSymbolAddress((void**)&pH,  g_h);
    cudaGetSymbolAddress((void**)&pZ1, g_z1);
    cudaGetSymbolAddress((void**)&pPH, g_PH);
    cudaGetSymbolAddress((void**)&pDH, g_DH);
    cudaGetSymbolAddress((void**)&pWgx,g_Wgx);
    cudaGetSymbolAddress((void**)&pWex,g_Wex);
    cudaGetSymbolAddress((void**)&pGb, g_gb);
    cudaGetSymbolAddress((void**)&pEb, g_eb);

    cudaFuncSetAttribute(seq_clu, cudaFuncAttributeMaxDynamicSharedMemorySize, SEQ_SMEM_BYTES);

    // 1. fold biases + transpose Kz
    bias_fold_k<<<9,128>>>(lstm_bias,lstm_kernel,enc_h_w,enc_h_b,phi_x_b);
    kz_transpose_k<<<128,256>>>(lstm_kernel);
    // 2. fused weights: W_gx = phi_x_w @ K_x ; W_ex = phi_x_w @ Wenc_x
    gemm_k<<<dim3(16,1),256>>>(phi_x_w,128,128, nullptr,0,0, lstm_kernel,1024, nullptr,0,
                               nullptr, pWgx,1024,0,0);
    gemm_k<<<dim3(2,1),256>>>(phi_x_w,128,128, nullptr,0,0, enc_h_w,128, nullptr,0,
                              nullptr, pWex,128,0,0);
    // 3. big input GEMMs (rows b*T+t)
    gemm_k<<<dim3(16,512),256>>>(x,128,128, nullptr,0,0, pWgx,1024, nullptr,0,
                                 pGb, pGx,1024,0,0);
    gemm_k<<<dim3(2,512),256>>>(x,128,128, nullptr,0,0, pWex,128, nullptr,0,
                                pEb, pEx,128,0,0);
    // 4. sequential recurrence (16 clusters x 8 CTAs, st.async exchanges)
    seq_clu<<<128,512,SEQ_SMEM_BYTES>>>(eps, enc_h_w, enc_mu_w,enc_mu_b, enc_sg_w,enc_sg_b,
                                        phi_z_w,phi_z_b, lstm_kernel, lstm_rec, out);
    // 5. prior epilogue (rows t*128+b)
    gemm_k<<<dim3(2,512),256>>>(pH,256,256, nullptr,0,0, prior_h_w,128, nullptr,0,
                                prior_h_b, pPH,128,1,0);
    gemm_k<<<dim3(2,512),256>>>(pPH,128,128, nullptr,0,0, prior_mu_w,128, nullptr,0,
                                prior_mu_b, out+OFF_PMU,128,0,1);
    gemm_k<<<dim3(2,512),256>>>(pPH,128,128, nullptr,0,0, prior_sg_w,128, nullptr,0,
                                prior_sg_b, out+OFF_PSG,128,2,1);
    // 6. dec epilogue: dec_in = [z1, h]
    gemm_k<<<dim3(2,512),256>>>(pZ1,128,128, pH,256,256, dec_h_w,128, dec_h_w+128*128,128,
                                dec_h_b, pDH,128,1,0);
    gemm_k<<<dim3(2,512),256>>>(pDH,128,128, nullptr,0,0, dec_mu_w,128, nullptr,0,
                                dec_mu_b, out+OFF_DMU,128,0,1);
    gemm_k<<<dim3(2,512),256>>>(pDH,128,128, nullptr,0,0, dec_sg_w,128, nullptr,0,
                                dec_sg_b, out+OFF_DSG,128,2,1);
}

// round 6
// speedup vs baseline: 6.5416x; 1.2474x over previous
#include <cuda_runtime.h>
#include <stdint.h>
#include <math.h>

#define Tt 512
#define SEQSZ (128*512*128)
#define OFF_EMU 16384
#define OFF_ESG (OFF_EMU + 1*SEQSZ)
#define OFF_DMU (OFF_EMU + 2*SEQSZ)
#define OFF_DSG (OFF_EMU + 3*SEQSZ)
#define OFF_PMU (OFF_EMU + 4*SEQSZ)
#define OFF_PSG (OFF_EMU + 5*SEQSZ)

// scratch (static device globals; no runtime alloc)
__device__ float g_Gx[65536*1024];  // row b*T+t: x-contrib to gates (+biases folded)
__device__ float g_Ex[65536*128];   // row b*T+t: x-contrib to enc_h preact (+biases folded)
__device__ float g_h [65536*256];   // row t*128+b: h INPUT at step t
__device__ float g_z1[65536*128];   // row t*128+b
__device__ float g_PH[65536*128];
__device__ float g_DH[65536*128];
__device__ float g_Wgx[128*1024];
__device__ float g_Wex[128*128];
__device__ float g_Kp[8*8*512*4];   // coalesced Kz: [((rank*8+u)*512+tid)*4+e]
__device__ float g_gb[1024];
__device__ float g_eb[128];

typedef unsigned long long ull;

__device__ __forceinline__ float softplus_(float x){ return fmaxf(x,0.f)+log1pf(expf(-fabsf(x))); }
__device__ __forceinline__ float sigmoid_(float x){ return 1.f/(1.f+expf(-x)); }

__device__ __forceinline__ ull pack2_(float v){
    ull r; asm("mov.b64 %0, {%1, %1};" : "=l"(r) : "f"(v)); return r;
}
__device__ __forceinline__ ull packf2_(float a, float b){
    ull r; asm("mov.b64 %0, {%1, %2};" : "=l"(r) : "f"(a), "f"(b)); return r;
}
__device__ __forceinline__ void ffma2_(ull &d, ull a, ull b){
    asm("fma.rn.f32x2 %0, %1, %2, %0;" : "+l"(d) : "l"(a), "l"(b));
}
__device__ __forceinline__ void unpack2_(ull v, float &lo, float &hi){
    asm("mov.b64 {%0, %1}, %2;" : "=f"(lo), "=f"(hi) : "l"(v));
}
__device__ __forceinline__ unsigned mapa_(unsigned addr, unsigned rank){
    unsigned r; asm("mapa.shared::cluster.u32 %0, %1, %2;" : "=r"(r) : "r"(addr), "r"(rank));
    return r;
}
__device__ __forceinline__ void st_async64_(unsigned daddr, unsigned mbar, ull v){
    asm volatile("st.async.weak.shared::cluster.mbarrier::complete_tx::bytes.b64 [%0], %1, [%2];"
        :: "r"(daddr), "l"(v), "r"(mbar) : "memory");
}
__device__ __forceinline__ void mbar_init_(unsigned mbar, unsigned cnt){
    asm volatile("mbarrier.init.shared.b64 [%0], %1;" :: "r"(mbar), "r"(cnt) : "memory");
}
__device__ __forceinline__ void mbar_expect_(unsigned mbar, unsigned bytes){
    asm volatile("mbarrier.arrive.expect_tx.shared.b64 _, [%0], %1;" :: "r"(mbar), "r"(bytes) : "memory");
}
__device__ __forceinline__ void mbar_wait_(unsigned mbar, unsigned parity){
    unsigned done;
    asm volatile("{\n\t.reg .pred p;\n\t"
        "mbarrier.try_wait.parity.acquire.cta.shared::cta.b64 p, [%1], %2;\n\t"
        "selp.b32 %0, 1, 0, p;\n\t}"
        : "=r"(done) : "r"(mbar), "r"(parity) : "memory");
    while(!done){
        asm volatile("{\n\t.reg .pred p;\n\t"
            "mbarrier.try_wait.parity.acquire.cta.shared::cta.b64 p, [%1], %2, 0x989680;\n\t"
            "selp.b32 %0, 1, 0, p;\n\t}"
            : "=r"(done) : "r"(mbar), "r"(parity) : "memory");
    }
}
#define CLUSTER_SYNC_() do{ \
    asm volatile("barrier.cluster.arrive.aligned;" ::: "memory"); \
    asm volatile("barrier.cluster.wait.aligned;" ::: "memory"); }while(0)

// ------------------------- tiled SGEMM (unchanged, passing) ----------------
__global__ __launch_bounds__(256) void gemm_k(
    const float* __restrict__ A1,int lda1,int K1,
    const float* __restrict__ A2,int lda2,int K2,
    const float* __restrict__ W1,int ldw1,
    const float* __restrict__ W2,int ldw2,
    const float* __restrict__ bias,
    float* __restrict__ out,int N,int act,int btmode)
{
    __shared__ __align__(16) float As[8][128];
    __shared__ __align__(16) float Ws[8][64];
    const int bm=blockIdx.y*128, bn=blockIdx.x*64;
    const int tid=threadIdx.x;
    const int ty=tid>>4, tx=tid&15;
    const int lr=tid>>1, lc=(tid&1)*4;
    const int wr=tid>>6, wc=tid&63;
    float acc[8][4];
    #pragma unroll
    for(int i=0;i<8;i++)
      #pragma unroll
      for(int j=0;j<4;j++) acc[i][j]=0.f;
    for(int seg=0;seg<2;seg++){
        const float* A = seg? A2:A1;
        if(A==nullptr) continue;
        const float* W = seg? W2:W1;
        const int lda=seg?lda2:lda1, ldw=seg?ldw2:ldw1, K=seg?K2:K1;
        for(int k0=0;k0<K;k0+=8){
            float4 av = *(const float4*)(A + (size_t)(bm+lr)*lda + k0+lc);
            float w0 = W[(size_t)(k0+wr)*ldw + bn+wc];
            float w1 = W[(size_t)(k0+wr+4)*ldw + bn+wc];
            __syncthreads();
            As[lc+0][lr]=av.x; As[lc+1][lr]=av.y; As[lc+2][lr]=av.z; As[lc+3][lr]=av.w;
            Ws[wr][wc]=w0; Ws[wr+4][wc]=w1;
            __syncthreads();
            #pragma unroll
            for(int kk=0;kk<8;kk++){
                float a[8],w[4];
                *(float4*)&a[0]=*(const float4*)&As[kk][ty*8];
                *(float4*)&a[4]=*(const float4*)&As[kk][ty*8+4];
                *(float4*)&w[0]=*(const float4*)&Ws[kk][tx*4];
                #pragma unroll
                for(int i=0;i<8;i++)
                  #pragma unroll
                  for(int j=0;j<4;j++) acc[i][j]=fmaf(a[i],w[j],acc[i][j]);
            }
        }
    }
    #pragma unroll
    for(int i=0;i<8;i++){
        int r=bm+ty*8+i;
        #pragma unroll
        for(int j=0;j<4;j++){
            int n=bn+tx*4+j;
            float v=acc[i][j];
            if(bias) v+=bias[n];
            if(act==1) v=fmaxf(v,0.f);
            else if(act==2) v=softplus_(v);
            size_t idx;
            if(btmode){ int b=r&127, t=r>>7; idx=((size_t)b*Tt+t)*(size_t)N+n; }
            else idx=(size_t)r*N+n;
            out[idx]=v;
        }
    }
}

// prep: Kz permuted-coalesced copy + bias folds, one launch
__global__ __launch_bounds__(256) void prep_k(
    const float* __restrict__ lstm_kernel,
    const float* __restrict__ lstm_bias,
    const float* __restrict__ enc_h_w,
    const float* __restrict__ enc_h_b,
    const float* __restrict__ phi_x_b)
{
    if(blockIdx.x < 512){
        int idx = blockIdx.x*256 + threadIdx.x;   // [0,131072)
        int e=idx&3, tid=(idx>>2)&511, u=(idx>>11)&7, rank=idx>>14;
        int dcol=tid&127, dseg=tid>>7;
        int gcol=(dcol>>5)*256 + rank*32 + (dcol&31);
        int k=dseg*32 + u*4 + e;
        g_Kp[idx] = lstm_kernel[(size_t)(128+k)*1024 + gcol];
    } else {
        int jj = (blockIdx.x-512)*256 + threadIdx.x;
        if(jj<1024){
            float s=lstm_bias[jj];
            for(int f=0;f<128;f++) s=fmaf(phi_x_b[f],lstm_kernel[f*1024+jj],s);
            g_gb[jj]=s;
        } else if(jj<1152){
            int j=jj-1024;
            float s=enc_h_b[j];
            for(int f=0;f<128;f++) s=fmaf(phi_x_b[f],enc_h_w[f*128+j],s);
            g_eb[j]=s;
        }
    }
}

// ---------------- cluster-distributed sequential recurrence ----------------
// SMEM layout (float offsets)
#define S_R    0        // R_s[256][128]
#define S_WE   32768    // Wenc_s[256][16]
#define S_WMU  36864
#define S_WSG  38912
#define S_WPZ  40960
#define S_HT   43008    // hT[2][256][8] double buffered
#define S_ET   47104    // eT[128][8]
#define S_ZT   48128
#define S_Z1T  49152
#define S_GP   50176    // gp[4][8][128]
#define S_AP   54272    // phase-a partials [512]
#define S_AP2  54784    // phase-b partials [512]
#define S_AP3  55296    // phase-c partials [512]
#define S_BIAS 55808    // mu_b[16], sg_b[16], pz_b[16]
#define S_MB   55856    // 4 mbarriers
#define S_TOTF 55872
#define SEQ_SMEM_BYTES (S_TOTF*4)

__global__ void __cluster_dims__(8,1,1) __launch_bounds__(512,1) seq_clu(
    const float* __restrict__ eps,
    const float* __restrict__ enc_h_w,
    const float* __restrict__ enc_mu_w, const float* __restrict__ enc_mu_b,
    const float* __restrict__ enc_sg_w, const float* __restrict__ enc_sg_b,
    const float* __restrict__ phi_z_w,  const float* __restrict__ phi_z_b,
    const float* __restrict__ lstm_kernel, const float* __restrict__ lstm_rec,
    float* __restrict__ out)
{
    extern __shared__ __align__(16) float sm[];
    float* R_s    = sm + S_R;
    float* Wenc_s = sm + S_WE;
    float* Wmu_s  = sm + S_WMU;
    float* Wsg_s  = sm + S_WSG;
    float* Wpz_s  = sm + S_WPZ;
    float* hT     = sm + S_HT;
    float* eT     = sm + S_ET;
    float* zT     = sm + S_ZT;
    float* z1T    = sm + S_Z1T;
    float* gp     = sm + S_GP;
    float* apA    = sm + S_AP;
    float* apB    = sm + S_AP2;
    float* apC    = sm + S_AP3;
    float* bias_s = sm + S_BIAS;

    const unsigned smb = (unsigned)__cvta_generic_to_shared(sm);
    const unsigned mbE  = smb + S_MB*4;
    const unsigned mbZ  = mbE + 8;
    const unsigned mbZ1 = mbE + 16;
    const unsigned mbH  = mbE + 24;

    const int tid  = threadIdx.x;
    const int rank = blockIdx.x & 7;
    const int cid  = blockIdx.x >> 3;

    // ---- load weight slices into SMEM ----
    for(int idx=tid; idx<256*128; idx+=512){
        int k=idx>>7, c=idx&127;
        int gcol=(c>>5)*256 + rank*32 + (c&31);
        R_s[idx] = lstm_rec[k*1024 + gcol];
    }
    for(int idx=tid; idx<256*16; idx+=512){
        int k=idx>>4, j=idx&15;
        Wenc_s[idx] = enc_h_w[(128+k)*128 + rank*16 + j];
    }
    for(int idx=tid; idx<128*16; idx+=512){
        int k=idx>>4, j=idx&15;
        Wmu_s[idx] = enc_mu_w[k*128 + rank*16 + j];
        Wsg_s[idx] = enc_sg_w[k*128 + rank*16 + j];
        Wpz_s[idx] = phi_z_w [k*128 + rank*16 + j];
    }
    if(tid<16){
        bias_s[tid]    = enc_mu_b[rank*16+tid];
        bias_s[16+tid] = enc_sg_b[rank*16+tid];
        bias_s[32+tid] = phi_z_b [rank*16+tid];
    }
    for(int idx=tid; idx<2*256*8; idx+=512) hT[idx]=0.f;
    if(tid==0){
        mbar_init_(mbE,1); mbar_init_(mbZ,1); mbar_init_(mbZ1,1); mbar_init_(mbH,1);
    }
    __syncthreads();
    CLUSTER_SYNC_();

    float c0_st = 0.f, c1_st = 0.f;  // cell states for tid<128: rows 2rp,2rp+1, col j

    const int dcol = tid & 127, dseg = tid >> 7;

    for(int t=0; t<Tt; t++){
        const unsigned par = t & 1;
        float* hTc = hT + (t&1)*2048;
        const unsigned hTn_off = (unsigned)(S_HT + ((t+1)&1)*2048);

        if(tid==0){
            mbar_expect_(mbE,4096); mbar_expect_(mbZ,4096);
            mbar_expect_(mbZ1,4096); mbar_expect_(mbH,8192);
        }

        // ---- prefetches (hidden behind phases a-c) ----
        float exv0=0.f,exv1=0.f,eps0=0.f,eps1=0.f;
        if(tid<64){
            int col=tid&15, rp=tid>>4;
            size_t b0 = ((size_t)(cid*8+2*rp  )*Tt + t)*128 + rank*16 + col;
            size_t b1 = ((size_t)(cid*8+2*rp+1)*Tt + t)*128 + rank*16 + col;
            exv0=g_Ex[b0]; exv1=g_Ex[b1]; eps0=eps[b0]; eps1=eps[b1];
        }
        float gxv[8];
        if(tid<128){
            int j=tid&31, rp=tid>>5;
            size_t gb0 = ((size_t)(cid*8+2*rp  )*Tt + t)*1024 + rank*32 + j;
            size_t gb1 = ((size_t)(cid*8+2*rp+1)*Tt + t)*1024 + rank*32 + j;
            #pragma unroll
            for(int g=0;g<4;g++){ gxv[g]=g_Gx[gb0+(size_t)g*256]; gxv[4+g]=g_Gx[gb1+(size_t)g*256]; }
        }
        float w32[32];
        {
            const float4* kp4 = (const float4*)g_Kp;
            #pragma unroll
            for(int u=0;u<8;u++) *(float4*)&w32[u*4] = __ldg(&kp4[(rank*8+u)*512 + tid]);
        }
        // store h input for prior/dec epilogues
        if(tid<256){
            int row=tid>>5, j=tid&31;
            g_h[((size_t)t*128 + cid*8 + row)*256 + rank*32 + j] = hTc[(rank*32+j)*8 + row];
        }

        // ---- (a) enc_h slice: relu(Ex + h @ Wenc_h) ----
        {
            int oc=tid&127, seg=tid>>7, row=oc>>4, col=oc&15;
            float s0=0.f, s1=0.f;
            int k0=seg*64;
            #pragma unroll 4
            for(int k=k0;k<k0+64;k+=2){
                s0 = fmaf(hTc[k*8+row],     Wenc_s[k*16+col],     s0);
                s1 = fmaf(hTc[(k+1)*8+row], Wenc_s[(k+1)*16+col], s1);
            }
            apA[tid]=s0+s1;
        }
        __syncthreads();
        if(tid<64){
            int col=tid&15, rp=tid>>4, r0=2*rp, r1=r0+1;
            int i0=r0*16+col, i1=r1*16+col;
            float v0 = apA[i0]+apA[i0+128]+apA[i0+256]+apA[i0+384] + exv0;
            float v1 = apA[i1]+apA[i1+128]+apA[i1+256]+apA[i1+384] + exv1;
            v0=fmaxf(v0,0.f); v1=fmaxf(v1,0.f);
            ull vv = packf2_(v0,v1);
            unsigned la = smb + (unsigned)(S_ET + (rank*16+col)*8 + r0)*4u;
            #pragma unroll
            for(unsigned rk=0;rk<8;rk++) st_async64_(mapa_(la,rk), mapa_(mbE,rk), vv);
        }
        mbar_wait_(mbE, par);

        // ---- (b) enc_mu / enc_sigma / z ----
        {
            int o=tid&255, seg=tid>>8, row=o>>5, col=(o>>1)&15, typ=o&1;
            const float* W = typ ? Wsg_s : Wmu_s;
            float s0=0.f, s1=0.f;
            int k0=seg*64;
            #pragma unroll 4
            for(int k=k0;k<k0+64;k+=2){
                s0 = fmaf(eT[k*8+row],     W[k*16+col],     s0);
                s1 = fmaf(eT[(k+1)*8+row], W[(k+1)*16+col], s1);
            }
            apB[tid]=s0+s1;
        }
        __syncthreads();
        if(tid<64){
            int col=tid&15, rp=tid>>4, r0=2*rp, r1=r0+1;
            int o0=(r0<<5)+(col<<1), o1=(r1<<5)+(col<<1);
            float mu0 = apB[o0]   + apB[o0+256]   + bias_s[col];
            float sg0 = softplus_(apB[o0+1] + apB[o0+257] + bias_s[16+col]);
            float mu1 = apB[o1]   + apB[o1+256]   + bias_s[col];
            float sg1 = softplus_(apB[o1+1] + apB[o1+257] + bias_s[16+col]);
            size_t b0 = ((size_t)(cid*8+r0)*Tt + t)*128 + rank*16 + col;
            size_t b1 = ((size_t)(cid*8+r1)*Tt + t)*128 + rank*16 + col;
            out[OFF_EMU+b0]=mu0; out[OFF_ESG+b0]=sg0;
            out[OFF_EMU+b1]=mu1; out[OFF_ESG+b1]=sg1;
            float z0 = fmaf(sg0, eps0, mu0);
            float z1v= fmaf(sg1, eps1, mu1);
            ull zz = packf2_(z0,z1v);
            unsigned la = smb + (unsigned)(S_ZT + (rank*16+col)*8 + r0)*4u;
            #pragma unroll
            for(unsigned rk=0;rk<8;rk++) st_async64_(mapa_(la,rk), mapa_(mbZ,rk), zz);
        }
        mbar_wait_(mbZ, par);

        // ---- (c) z1 = relu(z @ phi_z_w + b) ----
        {
            int oc=tid&127, seg=tid>>7, row=oc>>4, col=oc&15;
            float s0=0.f, s1=0.f;
            int k0=seg*32;
            #pragma unroll 4
            for(int k=k0;k<k0+32;k+=2){
                s0 = fmaf(zT[k*8+row],     Wpz_s[k*16+col],     s0);
                s1 = fmaf(zT[(k+1)*8+row], Wpz_s[(k+1)*16+col], s1);
            }
            apC[tid]=s0+s1;
        }
        __syncthreads();
        if(tid<64){
            int col=tid&15, rp=tid>>4, r0=2*rp, r1=r0+1;
            int i0=r0*16+col, i1=r1*16+col;
            float v0 = apC[i0]+apC[i0+128]+apC[i0+256]+apC[i0+384] + bias_s[32+col];
            float v1 = apC[i1]+apC[i1+128]+apC[i1+256]+apC[i1+384] + bias_s[32+col];
            v0=fmaxf(v0,0.f); v1=fmaxf(v1,0.f);
            g_z1[((size_t)t*128 + cid*8 + r0)*128 + rank*16 + col] = v0;
            g_z1[((size_t)t*128 + cid*8 + r1)*128 + rank*16 + col] = v1;
            if(t==Tt-1){
                out[(size_t)(cid*8+r0)*128 + rank*16 + col] = v0;
                out[(size_t)(cid*8+r1)*128 + rank*16 + col] = v1;
            }
            ull vv = packf2_(v0,v1);
            unsigned la = smb + (unsigned)(S_Z1T + (rank*16+col)*8 + r0)*4u;
            #pragma unroll
            for(unsigned rk=0;rk<8;rk++) st_async64_(mapa_(la,rk), mapa_(mbZ1,rk), vv);
        }

        // ---- (d1) h@R partial while z1 exchange is in flight ----
        ull a0=0ull,a1=0ull,a2=0ull,a3=0ull;
        {
            const int kr0=dseg*64;
            #pragma unroll 4
            for(int kk=kr0;kk<kr0+64;kk++){
                ull w2 = pack2_(R_s[kk*128+dcol]);
                const ulonglong2* hp = (const ulonglong2*)(hTc + kk*8);
                ulonglong2 p0 = hp[0], p1 = hp[1];
                ffma2_(a0,w2,p0.x); ffma2_(a1,w2,p0.y);
                ffma2_(a2,w2,p1.x); ffma2_(a3,w2,p1.y);
            }
        }
        mbar_wait_(mbZ1, par);

        // ---- (d2) z1@Kz from registers ----
        {
            const int kz0=dseg*32;
            #pragma unroll
            for(int u=0;u<32;u++){
                ull w2 = pack2_(w32[u]);
                const ulonglong2* zp = (const ulonglong2*)(z1T + (kz0+u)*8);
                ulonglong2 p0 = zp[0], p1 = zp[1];
                ffma2_(a0,w2,p0.x); ffma2_(a1,w2,p0.y);
                ffma2_(a2,w2,p1.x); ffma2_(a3,w2,p1.y);
            }
            float r0,r1,r2,r3,r4,r5,r6,r7;
            unpack2_(a0,r0,r1); unpack2_(a1,r2,r3);
            unpack2_(a2,r4,r5); unpack2_(a3,r6,r7);
            float* gpp = gp + dseg*1024 + dcol;
            gpp[0*128]=r0; gpp[1*128]=r1; gpp[2*128]=r2; gpp[3*128]=r3;
            gpp[4*128]=r4; gpp[5*128]=r5; gpp[6*128]=r6; gpp[7*128]=r7;
        }
        __syncthreads();
        if(tid<128){
            int j=tid&31, rp=tid>>5, r0=2*rp, r1=r0+1;
            float gi0=gxv[0], gf0=gxv[1], gg0=gxv[2], go0=gxv[3];
            float gi1=gxv[4], gf1=gxv[5], gg1=gxv[6], go1=gxv[7];
            #pragma unroll
            for(int s=0;s<4;s++){
                const float* p0 = gp + s*1024 + r0*128;
                const float* p1 = gp + s*1024 + r1*128;
                gi0+=p0[j]; gf0+=p0[32+j]; gg0+=p0[64+j]; go0+=p0[96+j];
                gi1+=p1[j]; gf1+=p1[32+j]; gg1+=p1[64+j]; go1+=p1[96+j];
            }
            float iv0=sigmoid_(gi0), fv0=sigmoid_(gf0), gv0=tanhf(gg0), ov0=sigmoid_(go0);
            float iv1=sigmoid_(gi1), fv1=sigmoid_(gf1), gv1=tanhf(gg1), ov1=sigmoid_(go1);
            c0_st = fv0*c0_st + iv0*gv0;
            c1_st = fv1*c1_st + iv1*gv1;
            float h0 = ov0*tanhf(c0_st);
            float h1 = ov1*tanhf(c1_st);
            ull hh = packf2_(h0,h1);
            unsigned la = smb + (hTn_off + (unsigned)((rank*32+j)*8 + r0))*4u;
            #pragma unroll
            for(unsigned rk=0;rk<8;rk++) st_async64_(mapa_(la,rk), mapa_(mbH,rk), hh);
        }
        mbar_wait_(mbH, par);
    }
    CLUSTER_SYNC_();
}

extern "C" void kernel_launch(void* const* d_in, const int* in_sizes, int n_in,
                              void* d_out, int out_size)
{
    (void)in_sizes;(void)n_in;(void)out_size;
    const float* x           =(const float*)d_in[0];
    const float* eps         =(const float*)d_in[1];
    const float* prior_h_w   =(const float*)d_in[2];
    const float* prior_h_b   =(const float*)d_in[3];
    const float* prior_mu_w  =(const float*)d_in[4];
    const float* prior_mu_b  =(const float*)d_in[5];
    const float* prior_sg_w  =(const float*)d_in[6];
    const float* prior_sg_b  =(const float*)d_in[7];
    const float* phi_x_w     =(const float*)d_in[8];
    const float* phi_x_b     =(const float*)d_in[9];
    const float* enc_h_w     =(const float*)d_in[10];
    const float* enc_h_b     =(const float*)d_in[11];
    const float* enc_mu_w    =(const float*)d_in[12];
    const float* enc_mu_b    =(const float*)d_in[13];
    const float* enc_sg_w    =(const float*)d_in[14];
    const float* enc_sg_b    =(const float*)d_in[15];
    const float* phi_z_w     =(const float*)d_in[16];
    const float* phi_z_b     =(const float*)d_in[17];
    const float* dec_h_w     =(const float*)d_in[18];
    const float* dec_h_b     =(const float*)d_in[19];
    const float* dec_mu_w    =(const float*)d_in[20];
    const float* dec_mu_b    =(const float*)d_in[21];
    const float* dec_sg_w    =(const float*)d_in[22];
    const float* dec_sg_b    =(const float*)d_in[23];
    const float* lstm_kernel =(const float*)d_in[24];
    const float* lstm_rec    =(const float*)d_in[25];
    const float* lstm_bias   =(const float*)d_in[26];
    float* out=(float*)d_out;

    float *pGx,*pEx,*pH,*pZ1,*pPH,*pDH,*pWgx,*pWex,*pGb,*pEb;
    cudaGetSymbolAddress((void**)&pGx, g_Gx);
    cudaGetSymbolAddress((void**)&pEx, g_Ex);
    cudaGetSymbolAddress((void**)&pH,  g_h);
    cudaGetSymbolAddress((void**)&pZ1, g_z1);
    cudaGetSymbolAddress((void**)&pPH, g_PH);
    cudaGetSymbolAddress((void**)&pDH, g_DH);
    cudaGetSymbolAddress((void**)&pWgx,g_Wgx);
    cudaGetSymbolAddress((void**)&pWex,g_Wex);
    cudaGetSymbolAddress((void**)&pGb, g_gb);
    cudaGetSymbolAddress((void**)&pEb, g_eb);

    cudaFuncSetAttribute(seq_clu, cudaFuncAttributeMaxDynamicSharedMemorySize, SEQ_SMEM_BYTES);

    // 1. prep (bias folds + coalesced Kz)
    prep_k<<<517,256>>>(lstm_kernel,lstm_bias,enc_h_w,enc_h_b,phi_x_b);
    // 2-3. fused weights
    gemm_k<<<dim3(16,1),256>>>(phi_x_w,128,128, nullptr,0,0, lstm_kernel,1024, nullptr,0,
                               nullptr, pWgx,1024,0,0);
    gemm_k<<<dim3(2,1),256>>>(phi_x_w,128,128, nullptr,0,0, enc_h_w,128, nullptr,0,
                              nullptr, pWex,128,0,0);
    // 4-5. big input GEMMs
    gemm_k<<<dim3(16,512),256>>>(x,128,128, nullptr,0,0, pWgx,1024, nullptr,0,
                                 pGb, pGx,1024,0,0);
    gemm_k<<<dim3(2,512),256>>>(x,128,128, nullptr,0,0, pWex,128, nullptr,0,
                                pEb, pEx,128,0,0);
    // 6. sequential recurrence  (launch #6 -> ncu -s 5 -c 1 captures THIS)
    seq_clu<<<128,512,SEQ_SMEM_BYTES>>>(eps, enc_h_w, enc_mu_w,enc_mu_b, enc_sg_w,enc_sg_b,
                                        phi_z_w,phi_z_b, lstm_kernel, lstm_rec, out);
    // 7-12. epilogues
    gemm_k<<<dim3(2,512),256>>>(pH,256,256, nullptr,0,0, prior_h_w,128, nullptr,0,
                                prior_h_b, pPH,128,1,0);
    gemm_k<<<dim3(2,512),256>>>(pPH,128,128, nullptr,0,0, prior_mu_w,128, nullptr,0,
                                prior_mu_b, out+OFF_PMU,128,0,1);
    gemm_k<<<dim3(2,512),256>>>(pPH,128,128, nullptr,0,0, prior_sg_w,128, nullptr,0,
                                prior_sg_b, out+OFF_PSG,128,2,1);
    gemm_k<<<dim3(2,512),256>>>(pZ1,128,128, pH,256,256, dec_h_w,128, dec_h_w+128*128,128,
                                dec_h_b, pDH,128,1,0);
    gemm_k<<<dim3(2,512),256>>>(pDH,128,128, nullptr,0,0, dec_mu_w,128, nullptr,0,
                                dec_mu_b, out+OFF_DMU,128,0,1);
    gemm_k<<<dim3(2,512),256>>>(pDH,128,128, nullptr,0,0, dec_sg_w,128, nullptr,0,
                                dec_sg_b, out+OFF_DSG,128,2,1);
}

// round 7
// speedup vs baseline: 7.4970x; 1.1460x over previous
#include <cuda_runtime.h>
#include <stdint.h>
#include <math.h>

#define Tt 512
#define SEQSZ (128*512*128)
#define OFF_EMU 16384
#define OFF_ESG (OFF_EMU + 1*SEQSZ)
#define OFF_DMU (OFF_EMU + 2*SEQSZ)
#define OFF_DSG (OFF_EMU + 3*SEQSZ)
#define OFF_PMU (OFF_EMU + 4*SEQSZ)
#define OFF_PSG (OFF_EMU + 5*SEQSZ)

// scratch (static device globals; no runtime alloc)
__device__ float g_Gx[65536*1024];  // row b*T+t: x-contrib to gates (+biases folded)
__device__ float g_Ex[65536*128];   // row b*T+t: x-contrib to enc_h preact (+biases folded)
__device__ float g_h [65536*256];   // row t*128+b: h INPUT at step t
__device__ float g_z1[65536*128];   // row t*128+b
__device__ float g_PH[65536*128];
__device__ float g_DH[65536*128];
__device__ float g_Wgx[128*1024];
__device__ float g_Wex[128*128];
__device__ float g_Kp[8*8*512*4];   // coalesced Kz: [((rank*8+u)*512+tid)*4+e]
__device__ float g_gb[1024];
__device__ float g_eb[128];

typedef unsigned long long ull;

__device__ __forceinline__ float softplus_(float x){ return fmaxf(x,0.f)+log1pf(expf(-fabsf(x))); }
__device__ __forceinline__ float sigmoid_(float x){ return 1.f/(1.f+expf(-x)); }

__device__ __forceinline__ ull pack2_(float v){
    ull r; asm("mov.b64 %0, {%1, %1};" : "=l"(r) : "f"(v)); return r;
}
__device__ __forceinline__ void ffma2_(ull &d, ull a, ull b){
    asm("fma.rn.f32x2 %0, %1, %2, %0;" : "+l"(d) : "l"(a), "l"(b));
}
__device__ __forceinline__ void unpack2_(ull v, float &lo, float &hi){
    asm("mov.b64 {%0, %1}, %2;" : "=f"(lo), "=f"(hi) : "l"(v));
}
__device__ __forceinline__ unsigned mapa_(unsigned addr, unsigned rank){
    unsigned r; asm("mapa.shared::cluster.u32 %0, %1, %2;" : "=r"(r) : "r"(addr), "r"(rank));
    return r;
}
// bulk SMEM->SMEM cluster copy, completion = complete_tx on dest-CTA mbarrier
__device__ __forceinline__ void blkcp_(unsigned dst, unsigned src, unsigned bytes, unsigned mbar){
    asm volatile("cp.async.bulk.shared::cluster.shared::cta.mbarrier::complete_tx::bytes [%0], [%1], %2, [%3];"
        :: "r"(dst), "r"(src), "r"(bytes), "r"(mbar) : "memory");
}
__device__ __forceinline__ void fence_async_(){
    asm volatile("fence.proxy.async.shared::cta;" ::: "memory");
}
__device__ __forceinline__ void mbar_init_(unsigned mbar, unsigned cnt){
    asm volatile("mbarrier.init.shared.b64 [%0], %1;" :: "r"(mbar), "r"(cnt) : "memory");
}
__device__ __forceinline__ void mbar_expect_(unsigned mbar, unsigned bytes){
    asm volatile("mbarrier.arrive.expect_tx.shared.b64 _, [%0], %1;" :: "r"(mbar), "r"(bytes) : "memory");
}
__device__ __forceinline__ void mbar_wait_(unsigned mbar, unsigned parity){
    unsigned done;
    asm volatile("{\n\t.reg .pred p;\n\t"
        "mbarrier.try_wait.parity.acquire.cta.shared::cta.b64 p, [%1], %2;\n\t"
        "selp.b32 %0, 1, 0, p;\n\t}"
        : "=r"(done) : "r"(mbar), "r"(parity) : "memory");
    while(!done){
        asm volatile("{\n\t.reg .pred p;\n\t"
            "mbarrier.try_wait.parity.acquire.cta.shared::cta.b64 p, [%1], %2, 0x989680;\n\t"
            "selp.b32 %0, 1, 0, p;\n\t}"
            : "=r"(done) : "r"(mbar), "r"(parity) : "memory");
    }
}
#define CLUSTER_SYNC_() do{ \
    asm volatile("barrier.cluster.arrive.aligned;" ::: "memory"); \
    asm volatile("barrier.cluster.wait.aligned;" ::: "memory"); }while(0)

// ------------------------- tiled SGEMM (unchanged, passing) ----------------
__global__ __launch_bounds__(256) void gemm_k(
    const float* __restrict__ A1,int lda1,int K1,
    const float* __restrict__ A2,int lda2,int K2,
    const float* __restrict__ W1,int ldw1,
    const float* __restrict__ W2,int ldw2,
    const float* __restrict__ bias,
    float* __restrict__ out,int N,int act,int btmode)
{
    __shared__ __align__(16) float As[8][128];
    __shared__ __align__(16) float Ws[8][64];
    const int bm=blockIdx.y*128, bn=blockIdx.x*64;
    const int tid=threadIdx.x;
    const int ty=tid>>4, tx=tid&15;
    const int lr=tid>>1, lc=(tid&1)*4;
    const int wr=tid>>6, wc=tid&63;
    float acc[8][4];
    #pragma unroll
    for(int i=0;i<8;i++)
      #pragma unroll
      for(int j=0;j<4;j++) acc[i][j]=0.f;
    for(int seg=0;seg<2;seg++){
        const float* A = seg? A2:A1;
        if(A==nullptr) continue;
        const float* W = seg? W2:W1;
        const int lda=seg?lda2:lda1, ldw=seg?ldw2:ldw1, K=seg?K2:K1;
        for(int k0=0;k0<K;k0+=8){
            float4 av = *(const float4*)(A + (size_t)(bm+lr)*lda + k0+lc);
            float w0 = W[(size_t)(k0+wr)*ldw + bn+wc];
            float w1 = W[(size_t)(k0+wr+4)*ldw + bn+wc];
            __syncthreads();
            As[lc+0][lr]=av.x; As[lc+1][lr]=av.y; As[lc+2][lr]=av.z; As[lc+3][lr]=av.w;
            Ws[wr][wc]=w0; Ws[wr+4][wc]=w1;
            __syncthreads();
            #pragma unroll
            for(int kk=0;kk<8;kk++){
                float a[8],w[4];
                *(float4*)&a[0]=*(const float4*)&As[kk][ty*8];
                *(float4*)&a[4]=*(const float4*)&As[kk][ty*8+4];
                *(float4*)&w[0]=*(const float4*)&Ws[kk][tx*4];
                #pragma unroll
                for(int i=0;i<8;i++)
                  #pragma unroll
                  for(int j=0;j<4;j++) acc[i][j]=fmaf(a[i],w[j],acc[i][j]);
            }
        }
    }
    #pragma unroll
    for(int i=0;i<8;i++){
        int r=bm+ty*8+i;
        #pragma unroll
        for(int j=0;j<4;j++){
            int n=bn+tx*4+j;
            float v=acc[i][j];
            if(bias) v+=bias[n];
            if(act==1) v=fmaxf(v,0.f);
            else if(act==2) v=softplus_(v);
            size_t idx;
            if(btmode){ int b=r&127, t=r>>7; idx=((size_t)b*Tt+t)*(size_t)N+n; }
            else idx=(size_t)r*N+n;
            out[idx]=v;
        }
    }
}

// prep: Kz permuted-coalesced copy + bias folds, one launch
__global__ __launch_bounds__(256) void prep_k(
    const float* __restrict__ lstm_kernel,
    const float* __restrict__ lstm_bias,
    const float* __restrict__ enc_h_w,
    const float* __restrict__ enc_h_b,
    const float* __restrict__ phi_x_b)
{
    if(blockIdx.x < 512){
        int idx = blockIdx.x*256 + threadIdx.x;   // [0,131072)
        int e=idx&3, tid=(idx>>2)&511, u=(idx>>11)&7, rank=idx>>14;
        int dcol=tid&127, dseg=tid>>7;
        int gcol=(dcol>>5)*256 + rank*32 + (dcol&31);
        int k=dseg*32 + u*4 + e;
        g_Kp[idx] = lstm_kernel[(size_t)(128+k)*1024 + gcol];
    } else {
        int jj = (blockIdx.x-512)*256 + threadIdx.x;
        if(jj<1024){
            float s=lstm_bias[jj];
            for(int f=0;f<128;f++) s=fmaf(phi_x_b[f],lstm_kernel[f*1024+jj],s);
            g_gb[jj]=s;
        } else if(jj<1152){
            int j=jj-1024;
            float s=enc_h_b[j];
            for(int f=0;f<128;f++) s=fmaf(phi_x_b[f],enc_h_w[f*128+j],s);
            g_eb[j]=s;
        }
    }
}

// ---------------- cluster-distributed sequential recurrence ----------------
// SMEM layout (float offsets)
#define S_R    0        // R_s[256][128]
#define S_WE   32768    // Wenc_s[256][16]
#define S_WMU  36864
#define S_WSG  38912
#define S_WPZ  40960
#define S_HT   43008    // hT[2][256][8] double buffered
#define S_ET   47104    // eT[128][8]  (slice for src rank r at float off r*128)
#define S_ZT   48128
#define S_Z1T  49152
#define S_GP   50176    // gp[4][8][128]
#define S_AP   54272    // shared partials [512] (reused by phases a,b,c)
#define S_BIAS 54784    // mu_b[16], sg_b[16], pz_b[16]
#define S_MB   54832    // 4 mbarriers (8 floats = 4x8B)
#define S_STA  54840    // stage a   [128]
#define S_STZ  54968    // stage z   [128]
#define S_STZ1 55096    // stage z1  [128]
#define S_STH  55224    // stage h   [256]
#define S_TOTF 55480
#define SEQ_SMEM_BYTES (S_TOTF*4)

__global__ void __cluster_dims__(8,1,1) __launch_bounds__(512,1) seq_clu(
    const float* __restrict__ eps,
    const float* __restrict__ enc_h_w,
    const float* __restrict__ enc_mu_w, const float* __restrict__ enc_mu_b,
    const float* __restrict__ enc_sg_w, const float* __restrict__ enc_sg_b,
    const float* __restrict__ phi_z_w,  const float* __restrict__ phi_z_b,
    const float* __restrict__ lstm_rec,
    float* __restrict__ out)
{
    extern __shared__ __align__(16) float sm[];
    float* R_s    = sm + S_R;
    float* Wenc_s = sm + S_WE;
    float* Wmu_s  = sm + S_WMU;
    float* Wsg_s  = sm + S_WSG;
    float* Wpz_s  = sm + S_WPZ;
    float* hT     = sm + S_HT;
    float* eT     = sm + S_ET;
    float* zT     = sm + S_ZT;
    float* z1T    = sm + S_Z1T;
    float* gp     = sm + S_GP;
    float* ap     = sm + S_AP;
    float* bias_s = sm + S_BIAS;
    float* stgA   = sm + S_STA;
    float* stgZ   = sm + S_STZ;
    float* stgZ1  = sm + S_STZ1;
    float* stgH   = sm + S_STH;

    const unsigned smb = (unsigned)__cvta_generic_to_shared(sm);
    const unsigned mbE  = smb + S_MB*4;
    const unsigned mbZ  = mbE + 8;
    const unsigned mbZ1 = mbE + 16;
    const unsigned mbH  = mbE + 24;

    const int tid  = threadIdx.x;
    const int rank = blockIdx.x & 7;
    const int cid  = blockIdx.x >> 3;

    // ---- load weight slices into SMEM ----
    for(int idx=tid; idx<256*128; idx+=512){
        int k=idx>>7, c=idx&127;
        int gcol=(c>>5)*256 + rank*32 + (c&31);
        R_s[idx] = lstm_rec[k*1024 + gcol];
    }
    for(int idx=tid; idx<256*16; idx+=512){
        int k=idx>>4, j=idx&15;
        Wenc_s[idx] = enc_h_w[(128+k)*128 + rank*16 + j];
    }
    for(int idx=tid; idx<128*16; idx+=512){
        int k=idx>>4, j=idx&15;
        Wmu_s[idx] = enc_mu_w[k*128 + rank*16 + j];
        Wsg_s[idx] = enc_sg_w[k*128 + rank*16 + j];
        Wpz_s[idx] = phi_z_w [k*128 + rank*16 + j];
    }
    if(tid<16){
        bias_s[tid]    = enc_mu_b[rank*16+tid];
        bias_s[16+tid] = enc_sg_b[rank*16+tid];
        bias_s[32+tid] = phi_z_b [rank*16+tid];
    }
    for(int idx=tid; idx<2*256*8; idx+=512) hT[idx]=0.f;
    if(tid==0){
        mbar_init_(mbE,1); mbar_init_(mbZ,1); mbar_init_(mbZ1,1); mbar_init_(mbH,1);
    }
    __syncthreads();
    CLUSTER_SYNC_();

    float c0_st = 0.f, c1_st = 0.f;  // cell states for tid<128: rows 2rp,2rp+1, col j

    const int dcol = tid & 127, dseg = tid >> 7;
    // local slice addresses (my slot inside every rank's buffers)
    const unsigned laE  = smb + (unsigned)S_ET*4u  + (unsigned)rank*512u;
    const unsigned laZ  = smb + (unsigned)S_ZT*4u  + (unsigned)rank*512u;
    const unsigned laZ1 = smb + (unsigned)S_Z1T*4u + (unsigned)rank*512u;
    const unsigned srcA  = smb + (unsigned)S_STA*4u;
    const unsigned srcZ  = smb + (unsigned)S_STZ*4u;
    const unsigned srcZ1 = smb + (unsigned)S_STZ1*4u;
    const unsigned srcH  = smb + (unsigned)S_STH*4u;

    for(int t=0; t<Tt; t++){
        const unsigned par = t & 1;
        float* hTc = hT + (t&1)*2048;
        const unsigned hTn_off = (unsigned)(S_HT + ((t+1)&1)*2048);

        if(tid==0){
            mbar_expect_(mbE,4096); mbar_expect_(mbZ,4096);
            mbar_expect_(mbZ1,4096); mbar_expect_(mbH,8192);
        }

        // ---- prefetches (hidden behind phases a-c) ----
        float exv0=0.f,exv1=0.f,eps0=0.f,eps1=0.f;
        if(tid<64){
            int col=tid&15, rp=tid>>4;
            size_t b0 = ((size_t)(cid*8+2*rp  )*Tt + t)*128 + rank*16 + col;
            size_t b1 = ((size_t)(cid*8+2*rp+1)*Tt + t)*128 + rank*16 + col;
            exv0=g_Ex[b0]; exv1=g_Ex[b1]; eps0=eps[b0]; eps1=eps[b1];
        }
        float gxv[8];
        if(tid<128){
            int j=tid&31, rp=tid>>5;
            size_t gb0 = ((size_t)(cid*8+2*rp  )*Tt + t)*1024 + rank*32 + j;
            size_t gb1 = ((size_t)(cid*8+2*rp+1)*Tt + t)*1024 + rank*32 + j;
            #pragma unroll
            for(int g=0;g<4;g++){ gxv[g]=g_Gx[gb0+(size_t)g*256]; gxv[4+g]=g_Gx[gb1+(size_t)g*256]; }
        }
        float w32[32];
        {
            const float4* kp4 = (const float4*)g_Kp;
            #pragma unroll
            for(int u=0;u<8;u++) *(float4*)&w32[u*4] = __ldg(&kp4[(rank*8+u)*512 + tid]);
        }
        // store h input for prior/dec epilogues
        if(tid<256){
            int row=tid>>5, j=tid&31;
            g_h[((size_t)t*128 + cid*8 + row)*256 + rank*32 + j] = hTc[(rank*32+j)*8 + row];
        }

        // ---- (a) enc_h slice: relu(Ex + h @ Wenc_h) ----
        {
            int oc=tid&127, seg=tid>>7, row=oc>>4, col=oc&15;
            float s0=0.f, s1=0.f;
            int k0=seg*64;
            #pragma unroll 4
            for(int k=k0;k<k0+64;k+=2){
                s0 = fmaf(hTc[k*8+row],     Wenc_s[k*16+col],     s0);
                s1 = fmaf(hTc[(k+1)*8+row], Wenc_s[(k+1)*16+col], s1);
            }
            ap[tid]=s0+s1;
        }
        __syncthreads();
        if(tid<64){
            int col=tid&15, rp=tid>>4, r0=2*rp, r1=r0+1;
            int i0=r0*16+col, i1=r1*16+col;
            float v0 = ap[i0]+ap[i0+128]+ap[i0+256]+ap[i0+384] + exv0;
            float v1 = ap[i1]+ap[i1+128]+ap[i1+256]+ap[i1+384] + exv1;
            stgA[col*8+r0]=fmaxf(v0,0.f);
            stgA[col*8+r1]=fmaxf(v1,0.f);
        }
        __syncthreads();
        if(tid==0){
            fence_async_();
            #pragma unroll
            for(unsigned rk=0;rk<8;rk++) blkcp_(mapa_(laE,rk), srcA, 512u, mapa_(mbE,rk));
        }
        mbar_wait_(mbE, par);

        // ---- (b) enc_mu / enc_sigma / z ----
        {
            int o=tid&255, seg=tid>>8, row=o>>5, col=(o>>1)&15, typ=o&1;
            const float* W = typ ? Wsg_s : Wmu_s;
            float s0=0.f, s1=0.f;
            int k0=seg*64;
            #pragma unroll 4
            for(int k=k0;k<k0+64;k+=2){
                s0 = fmaf(eT[k*8+row],     W[k*16+col],     s0);
                s1 = fmaf(eT[(k+1)*8+row], W[(k+1)*16+col], s1);
            }
            ap[tid]=s0+s1;
        }
        __syncthreads();
        if(tid<64){
            int col=tid&15, rp=tid>>4, r0=2*rp, r1=r0+1;
            int o0=(r0<<5)+(col<<1), o1=(r1<<5)+(col<<1);
            float mu0 = ap[o0]   + ap[o0+256]   + bias_s[col];
            float sg0 = softplus_(ap[o0+1] + ap[o0+257] + bias_s[16+col]);
            float mu1 = ap[o1]   + ap[o1+256]   + bias_s[col];
            float sg1 = softplus_(ap[o1+1] + ap[o1+257] + bias_s[16+col]);
            size_t b0 = ((size_t)(cid*8+r0)*Tt + t)*128 + rank*16 + col;
            size_t b1 = ((size_t)(cid*8+r1)*Tt + t)*128 + rank*16 + col;
            out[OFF_EMU+b0]=mu0; out[OFF_ESG+b0]=sg0;
            out[OFF_EMU+b1]=mu1; out[OFF_ESG+b1]=sg1;
            stgZ[col*8+r0]=fmaf(sg0, eps0, mu0);
            stgZ[col*8+r1]=fmaf(sg1, eps1, mu1);
        }
        __syncthreads();
        if(tid==0){
            fence_async_();
            #pragma unroll
            for(unsigned rk=0;rk<8;rk++) blkcp_(mapa_(laZ,rk), srcZ, 512u, mapa_(mbZ,rk));
        }
        mbar_wait_(mbZ, par);

        // ---- (c) z1 = relu(z @ phi_z_w + b) ----
        {
            int oc=tid&127, seg=tid>>7, row=oc>>4, col=oc&15;
            float s0=0.f, s1=0.f;
            int k0=seg*32;
            #pragma unroll 4
            for(int k=k0;k<k0+32;k+=2){
                s0 = fmaf(zT[k*8+row],     Wpz_s[k*16+col],     s0);
                s1 = fmaf(zT[(k+1)*8+row], Wpz_s[(k+1)*16+col], s1);
            }
            ap[tid]=s0+s1;
        }
        __syncthreads();
        if(tid<64){
            int col=tid&15, rp=tid>>4, r0=2*rp, r1=r0+1;
            int i0=r0*16+col, i1=r1*16+col;
            float v0 = ap[i0]+ap[i0+128]+ap[i0+256]+ap[i0+384] + bias_s[32+col];
            float v1 = ap[i1]+ap[i1+128]+ap[i1+256]+ap[i1+384] + bias_s[32+col];
            v0=fmaxf(v0,0.f); v1=fmaxf(v1,0.f);
            g_z1[((size_t)t*128 + cid*8 + r0)*128 + rank*16 + col] = v0;
            g_z1[((size_t)t*128 + cid*8 + r1)*128 + rank*16 + col] = v1;
            if(t==Tt-1){
                out[(size_t)(cid*8+r0)*128 + rank*16 + col] = v0;
                out[(size_t)(cid*8+r1)*128 + rank*16 + col] = v1;
            }
            stgZ1[col*8+r0]=v0;
            stgZ1[col*8+r1]=v1;
        }
        __syncthreads();
        if(tid==0){
            fence_async_();
            #pragma unroll
            for(unsigned rk=0;rk<8;rk++) blkcp_(mapa_(laZ1,rk), srcZ1, 512u, mapa_(mbZ1,rk));
        }

        // ---- (d1) h@R partial while z1 exchange is in flight ----
        ull a0=0ull,a1=0ull,a2=0ull,a3=0ull;
        {
            const int kr0=dseg*64;
            #pragma unroll 4
            for(int kk=kr0;kk<kr0+64;kk++){
                ull w2 = pack2_(R_s[kk*128+dcol]);
                const ulonglong2* hp = (const ulonglong2*)(hTc + kk*8);
                ulonglong2 p0 = hp[0], p1 = hp[1];
                ffma2_(a0,w2,p0.x); ffma2_(a1,w2,p0.y);
                ffma2_(a2,w2,p1.x); ffma2_(a3,w2,p1.y);
            }
        }
        mbar_wait_(mbZ1, par);

        // ---- (d2) z1@Kz from registers ----
        {
            const int kz0=dseg*32;
            #pragma unroll
            for(int u=0;u<32;u++){
                ull w2 = pack2_(w32[u]);
                const ulonglong2* zp = (const ulonglong2*)(z1T + (kz0+u)*8);
                ulonglong2 p0 = zp[0], p1 = zp[1];
                ffma2_(a0,w2,p0.x); ffma2_(a1,w2,p0.y);
                ffma2_(a2,w2,p1.x); ffma2_(a3,w2,p1.y);
            }
            float r0,r1,r2,r3,r4,r5,r6,r7;
            unpack2_(a0,r0,r1); unpack2_(a1,r2,r3);
            unpack2_(a2,r4,r5); unpack2_(a3,r6,r7);
            float* gpp = gp + dseg*1024 + dcol;
            gpp[0*128]=r0; gpp[1*128]=r1; gpp[2*128]=r2; gpp[3*128]=r3;
            gpp[4*128]=r4; gpp[5*128]=r5; gpp[6*128]=r6; gpp[7*128]=r7;
        }
        __syncthreads();
        if(tid<128){
            int j=tid&31, rp=tid>>5, r0=2*rp, r1=r0+1;
            float gi0=gxv[0], gf0=gxv[1], gg0=gxv[2], go0=gxv[3];
            float gi1=gxv[4], gf1=gxv[5], gg1=gxv[6], go1=gxv[7];
            #pragma unroll
            for(int s=0;s<4;s++){
                const float* p0 = gp + s*1024 + r0*128;
                const float* p1 = gp + s*1024 + r1*128;
                gi0+=p0[j]; gf0+=p0[32+j]; gg0+=p0[64+j]; go0+=p0[96+j];
                gi1+=p1[j]; gf1+=p1[32+j]; gg1+=p1[64+j]; go1+=p1[96+j];
            }
            float iv0=sigmoid_(gi0), fv0=sigmoid_(gf0), gv0=tanhf(gg0), ov0=sigmoid_(go0);
            float iv1=sigmoid_(gi1), fv1=sigmoid_(gf1), gv1=tanhf(gg1), ov1=sigmoid_(go1);
            c0_st = fv0*c0_st + iv0*gv0;
            c1_st = fv1*c1_st + iv1*gv1;
            stgH[j*8+r0] = ov0*tanhf(c0_st);
            stgH[j*8+r1] = ov1*tanhf(c1_st);
        }
        __syncthreads();
        if(tid==0){
            fence_async_();
            unsigned laH = smb + (hTn_off + (unsigned)rank*256u)*4u;
            #pragma unroll
            for(unsigned rk=0;rk<8;rk++) blkcp_(mapa_(laH,rk), srcH, 1024u, mapa_(mbH,rk));
        }
        mbar_wait_(mbH, par);
    }
    CLUSTER_SYNC_();
}

extern "C" void kernel_launch(void* const* d_in, const int* in_sizes, int n_in,
                              void* d_out, int out_size)
{
    (void)in_sizes;(void)n_in;(void)out_size;
    const float* x           =(const float*)d_in[0];
    const float* eps         =(const float*)d_in[1];
    const float* prior_h_w   =(const float*)d_in[2];
    const float* prior_h_b   =(const float*)d_in[3];
    const float* prior_mu_w  =(const float*)d_in[4];
    const float* prior_mu_b  =(const float*)d_in[5];
    const float* prior_sg_w  =(const float*)d_in[6];
    const float* prior_sg_b  =(const float*)d_in[7];
    const float* phi_x_w     =(const float*)d_in[8];
    const float* phi_x_b     =(const float*)d_in[9];
    const float* enc_h_w     =(const float*)d_in[10];
    const float* enc_h_b     =(const float*)d_in[11];
    const float* enc_mu_w    =(const float*)d_in[12];
    const float* enc_mu_b    =(const float*)d_in[13];
    const float* enc_sg_w    =(const float*)d_in[14];
    const float* enc_sg_b    =(const float*)d_in[15];
    const float* phi_z_w     =(const float*)d_in[16];
    const float* phi_z_b     =(const float*)d_in[17];
    const float* dec_h_w     =(const float*)d_in[18];
    const float* dec_h_b     =(const float*)d_in[19];
    const float* dec_mu_w    =(const float*)d_in[20];
    const float* dec_mu_b    =(const float*)d_in[21];
    const float* dec_sg_w    =(const float*)d_in[22];
    const float* dec_sg_b    =(const float*)d_in[23];
    const float* lstm_kernel =(const float*)d_in[24];
    const float* lstm_rec    =(const float*)d_in[25];
    const float* lstm_bias   =(const float*)d_in[26];
    float* out=(float*)d_out;

    float *pGx,*pEx,*pH,*pZ1,*pPH,*pDH,*pWgx,*pWex,*pGb,*pEb;
    cudaGetSymbolAddress((void**)&pGx, g_Gx);
    cudaGetSymbolAddress((void**)&pEx, g_Ex);
    cudaGetSymbolAddress((void**)&pH,  g_h);
    cudaGetSymbolAddress((void**)&pZ1, g_z1);
    cudaGetSymbolAddress((void**)&pPH, g_PH);
    cudaGetSymbolAddress((void**)&pDH, g_DH);
    cudaGetSymbolAddress((void**)&pWgx,g_Wgx);
    cudaGetSymbolAddress((void**)&pWex,g_Wex);
    cudaGetSymbolAddress((void**)&pGb, g_gb);
    cudaGetSymbolAddress((void**)&pEb, g_eb);

    cudaFuncSetAttribute(seq_clu, cudaFuncAttributeMaxDynamicSharedMemorySize, SEQ_SMEM_BYTES);

    // 1. prep (bias folds + coalesced Kz)
    prep_k<<<517,256>>>(lstm_kernel,lstm_bias,enc_h_w,enc_h_b,phi_x_b);
    // 2-3. fused weights
    gemm_k<<<dim3(16,1),256>>>(phi_x_w,128,128, nullptr,0,0, lstm_kernel,1024, nullptr,0,
                               nullptr, pWgx,1024,0,0);
    gemm_k<<<dim3(2,1),256>>>(phi_x_w,128,128, nullptr,0,0, enc_h_w,128, nullptr,0,
                              nullptr, pWex,128,0,0);
    // 4-5. big input GEMMs
    gemm_k<<<dim3(16,512),256>>>(x,128,128, nullptr,0,0, pWgx,1024, nullptr,0,
                                 pGb, pGx,1024,0,0);
    gemm_k<<<dim3(2,512),256>>>(x,128,128, nullptr,0,0, pWex,128, nullptr,0,
                                pEb, pEx,128,0,0);
    // 6. sequential recurrence (bulk-copy exchanges)
    seq_clu<<<128,512,SEQ_SMEM_BYTES>>>(eps, enc_h_w, enc_mu_w,enc_mu_b, enc_sg_w,enc_sg_b,
                                        phi_z_w,phi_z_b, lstm_rec, out);
    // 7-12. epilogues
    gemm_k<<<dim3(2,512),256>>>(pH,256,256, nullptr,0,0, prior_h_w,128, nullptr,0,
                                prior_h_b, pPH,128,1,0);
    gemm_k<<<dim3(2,512),256>>>(pPH,128,128, nullptr,0,0, prior_mu_w,128, nullptr,0,
                                prior_mu_b, out+OFF_PMU,128,0,1);
    gemm_k<<<dim3(2,512),256>>>(pPH,128,128, nullptr,0,0, prior_sg_w,128, nullptr,0,
                                prior_sg_b, out+OFF_PSG,128,2,1);
    gemm_k<<<dim3(2,512),256>>>(pZ1,128,128, pH,256,256, dec_h_w,128, dec_h_w+128*128,128,
                                dec_h_b, pDH,128,1,0);
    gemm_k<<<dim3(2,512),256>>>(pDH,128,128, nullptr,0,0, dec_mu_w,128, nullptr,0,
                                dec_mu_b, out+OFF_DMU,128,0,1);
    gemm_k<<<dim3(2,512),256>>>(pDH,128,128, nullptr,0,0, dec_sg_w,128, nullptr,0,
                                dec_sg_b, out+OFF_DSG,128,2,1);
}